// round 13
// baseline (speedup 1.0000x reference)
#include <cuda_runtime.h>
#include <cuda_bf16.h>
#include <cuda_fp16.h>
#include <stdint.h>

#define ELEMS ((size_t)4*256*256*128)   // 33.5M

// ---------------- scratch ----------------
__device__ __align__(16) __nv_bfloat16 g_at_hi[ELEMS];
__device__ __align__(16) __nv_bfloat16 g_at_lo[ELEMS];
__device__ __align__(16) __nv_bfloat16 g_bt_hi[ELEMS];
__device__ __align__(16) __nv_bfloat16 g_bt_lo[ELEMS];
__device__ __align__(16) __half g_gate[ELEMS];   // fp16: sigmoid in (0,1)
__device__ __align__(16) __half g_ot[ELEMS];     // fp16: LN-normalized downstream
// pre-split weight tile images: 6 mats x (hi 34816 B + lo 34816 B), 272 B row stride
__device__ __align__(16) unsigned char g_wt[6 * 69632];

// ---------------- helpers ----------------
__device__ __forceinline__ uint32_t smem_u32(const void* p){
    uint32_t a;
    asm("{ .reg .u64 t; cvta.to.shared.u64 t, %1; cvt.u32.u64 %0, t; }" : "=r"(a) : "l"(p));
    return a;
}
__device__ __forceinline__ void ldsm_x4(uint32_t* r, uint32_t a){
    asm volatile("ldmatrix.sync.aligned.m8n8.x4.shared.b16 {%0,%1,%2,%3}, [%4];"
        : "=r"(r[0]), "=r"(r[1]), "=r"(r[2]), "=r"(r[3]) : "r"(a));
}
__device__ __forceinline__ void mma16816(float* c, const uint32_t* a, const uint32_t* b){
    asm volatile("mma.sync.aligned.m16n8k16.row.col.f32.bf16.bf16.f32 "
        "{%0,%1,%2,%3}, {%4,%5,%6,%7}, {%8,%9}, {%0,%1,%2,%3};"
        : "+f"(c[0]), "+f"(c[1]), "+f"(c[2]), "+f"(c[3])
        : "r"(a[0]), "r"(a[1]), "r"(a[2]), "r"(a[3]), "r"(b[0]), "r"(b[1]));
}
__device__ __forceinline__ void cp16(uint32_t dst, const void* src){
    asm volatile("cp.async.cg.shared.global [%0], [%1], 16;" :: "r"(dst), "l"(src));
}
__device__ __forceinline__ void cp_commit(){
    asm volatile("cp.async.commit_group;" ::: "memory");
}
__device__ __forceinline__ void cp_wait0(){
    asm volatile("cp.async.wait_group 0;" ::: "memory");
}
__device__ __forceinline__ float sigmoidf_(float x){ return 1.0f / (1.0f + __expf(-x)); }
__device__ __forceinline__ uint16_t bf16bits(float v){
    __nv_bfloat16 h = __float2bfloat16(v);
    return *reinterpret_cast<uint16_t*>(&h);
}
__device__ __forceinline__ float bf2f(uint16_t u){
    __nv_bfloat16 h = *reinterpret_cast<__nv_bfloat16*>(&u);
    return __bfloat162float(h);
}
__device__ __forceinline__ void split4(float4 v, uint2& hh, uint2& ll){
    uint16_t h0=bf16bits(v.x), h1=bf16bits(v.y), h2=bf16bits(v.z), h3=bf16bits(v.w);
    uint16_t l0=bf16bits(v.x-bf2f(h0)), l1=bf16bits(v.y-bf2f(h1)),
             l2=bf16bits(v.z-bf2f(h2)), l3=bf16bits(v.w-bf2f(h3));
    hh.x = (uint32_t)h0 | ((uint32_t)h1<<16); hh.y = (uint32_t)h2 | ((uint32_t)h3<<16);
    ll.x = (uint32_t)l0 | ((uint32_t)l1<<16); ll.y = (uint32_t)l2 | ((uint32_t)l3<<16);
}

#define TSTRIDE 272u   // full-K (128) bf16 tile row stride in bytes
#define HSTRIDE 144u   // half-K (64)  bf16 tile row stride in bytes

// 32x32 warp-tile split GEMM over 64 K (4 ksteps). acc[2 m-subtiles][4 n-octets][4].
template<int SA, int SB>
__device__ __forceinline__ void gemm32(float (&acc)[2][4][4],
    uint32_t aHi, uint32_t aLo, uint32_t bHi, uint32_t bLo, int lane)
{
    const uint32_t aOff = (uint32_t)(lane & 15) * SA + (uint32_t)((lane >> 4) << 4);
    const uint32_t bOff = (uint32_t)(((lane >> 4) << 3) + (lane & 7)) * SB
                        + (uint32_t)(((lane >> 3) & 1) << 4);
    #pragma unroll
    for (int ks = 0; ks < 4; ks++) {
        const uint32_t ka = aOff + (uint32_t)ks * 32u;
        const uint32_t kb = bOff + (uint32_t)ks * 32u;
        uint32_t ah[2][4], al[2][4], bb[2][4];
        ldsm_x4(ah[0], aHi + ka);
        ldsm_x4(ah[1], aHi + 16u * SA + ka);
        ldsm_x4(bb[0], bHi + kb);
        ldsm_x4(bb[1], bHi + 16u * SB + kb);
        #pragma unroll
        for (int mt = 0; mt < 2; mt++)
            #pragma unroll
            for (int q = 0; q < 4; q++)
                mma16816(acc[mt][q], ah[mt], &bb[q >> 1][(q & 1) << 1]);
        ldsm_x4(al[0], aLo + ka);
        ldsm_x4(al[1], aLo + 16u * SA + ka);
        #pragma unroll
        for (int mt = 0; mt < 2; mt++)
            #pragma unroll
            for (int q = 0; q < 4; q++)
                mma16816(acc[mt][q], al[mt], &bb[q >> 1][(q & 1) << 1]);
        ldsm_x4(bb[0], bLo + kb);
        ldsm_x4(bb[1], bLo + 16u * SB + kb);
        #pragma unroll
        for (int mt = 0; mt < 2; mt++)
            #pragma unroll
            for (int q = 0; q < 4; q++)
                mma16816(acc[mt][q], ah[mt], &bb[q >> 1][(q & 1) << 1]);
    }
}

// pair GEMM: shared A-fragments drive TWO 32x32 warp tiles (G and P matrices).
__device__ __forceinline__ void gemm_pair(float (&aG)[2][4][4], float (&aP)[2][4][4],
    uint32_t aHi, uint32_t aLo, uint32_t gHi, uint32_t gLo,
    uint32_t pHi, uint32_t pLo, int lane)
{
    const uint32_t aOff = (uint32_t)(lane & 15) * TSTRIDE + (uint32_t)((lane >> 4) << 4);
    const uint32_t bOff = (uint32_t)(((lane >> 4) << 3) + (lane & 7)) * HSTRIDE
                        + (uint32_t)(((lane >> 3) & 1) << 4);
    #pragma unroll
    for (int ks = 0; ks < 4; ks++) {
        const uint32_t ka = aOff + (uint32_t)ks * 32u;
        const uint32_t kb = bOff + (uint32_t)ks * 32u;
        uint32_t ah[2][4], al[2][4], bb[2][4];
        ldsm_x4(ah[0], aHi + ka);
        ldsm_x4(ah[1], aHi + 16u * TSTRIDE + ka);
        ldsm_x4(al[0], aLo + ka);
        ldsm_x4(al[1], aLo + 16u * TSTRIDE + ka);
        // ---- G ----
        ldsm_x4(bb[0], gHi + kb);
        ldsm_x4(bb[1], gHi + 16u * HSTRIDE + kb);
        #pragma unroll
        for (int mt = 0; mt < 2; mt++)
            #pragma unroll
            for (int q = 0; q < 4; q++)
                mma16816(aG[mt][q], ah[mt], &bb[q >> 1][(q & 1) << 1]);
        #pragma unroll
        for (int mt = 0; mt < 2; mt++)
            #pragma unroll
            for (int q = 0; q < 4; q++)
                mma16816(aG[mt][q], al[mt], &bb[q >> 1][(q & 1) << 1]);
        ldsm_x4(bb[0], gLo + kb);
        ldsm_x4(bb[1], gLo + 16u * HSTRIDE + kb);
        #pragma unroll
        for (int mt = 0; mt < 2; mt++)
            #pragma unroll
            for (int q = 0; q < 4; q++)
                mma16816(aG[mt][q], ah[mt], &bb[q >> 1][(q & 1) << 1]);
        // ---- P ----
        ldsm_x4(bb[0], pHi + kb);
        ldsm_x4(bb[1], pHi + 16u * HSTRIDE + kb);
        #pragma unroll
        for (int mt = 0; mt < 2; mt++)
            #pragma unroll
            for (int q = 0; q < 4; q++)
                mma16816(aP[mt][q], ah[mt], &bb[q >> 1][(q & 1) << 1]);
        #pragma unroll
        for (int mt = 0; mt < 2; mt++)
            #pragma unroll
            for (int q = 0; q < 4; q++)
                mma16816(aP[mt][q], al[mt], &bb[q >> 1][(q & 1) << 1]);
        ldsm_x4(bb[0], pLo + kb);
        ldsm_x4(bb[1], pLo + 16u * HSTRIDE + kb);
        #pragma unroll
        for (int mt = 0; mt < 2; mt++)
            #pragma unroll
            for (int q = 0; q < 4; q++)
                mma16816(aP[mt][q], ah[mt], &bb[q >> 1][(q & 1) << 1]);
    }
}

// async copy one half-K (64k) weight tile (hi + lo planes), 256-thread blocks
__device__ __forceinline__ void load_w_half(uint32_t dst, int mat, int half){
    const unsigned char* src = g_wt + (size_t)mat * 69632 + half * 128;
    #pragma unroll
    for (int it = 0; it < 8; it++) {
        int lin = threadIdx.x + it * 256;      // 0..2047
        int plane = lin >> 10, idx = lin & 1023;
        int r = idx >> 3, c = idx & 7;
        cp16(dst + (uint32_t)plane * 18432u + (uint32_t)r * HSTRIDE + (uint32_t)c * 16u,
             src + (size_t)plane * 34816 + (size_t)r * 272 + c * 16);
    }
    cp_commit();
}

// LN one row (128 cols) by a full warp; write split bf16 into A tile (272B stride).
__device__ __forceinline__ void ln_row(char* smp, uint32_t hiOff, uint32_t loOff,
    int row, int lane, const float* x,
    float g0, float g1, float g2, float g3,
    float c0, float c1, float c2, float c3)
{
    float v0 = x[lane], v1 = x[lane+32], v2 = x[lane+64], v3 = x[lane+96];
    float s = v0 + v1 + v2 + v3;
    #pragma unroll
    for (int o = 16; o > 0; o >>= 1) s += __shfl_xor_sync(0xffffffffu, s, o);
    float mean = s * (1.0f / 128.0f);
    float d0 = v0-mean, d1 = v1-mean, d2 = v2-mean, d3 = v3-mean;
    float q = d0*d0 + d1*d1 + d2*d2 + d3*d3;
    #pragma unroll
    for (int o = 16; o > 0; o >>= 1) q += __shfl_xor_sync(0xffffffffu, q, o);
    float inv = rsqrtf(q * (1.0f / 128.0f) + 1e-5f);
    float y0 = d0*inv*g0 + c0, y1 = d1*inv*g1 + c1;
    float y2 = d2*inv*g2 + c2, y3 = d3*inv*g3 + c3;
    uint16_t* aH = (uint16_t*)(smp + hiOff);
    uint16_t* aL = (uint16_t*)(smp + loOff);
    uint16_t h;
    h = bf16bits(y0); aH[row*136 + lane]      = h; aL[row*136 + lane]      = bf16bits(y0 - bf2f(h));
    h = bf16bits(y1); aH[row*136 + lane + 32] = h; aL[row*136 + lane + 32] = bf16bits(y1 - bf2f(h));
    h = bf16bits(y2); aH[row*136 + lane + 64] = h; aL[row*136 + lane + 64] = bf16bits(y2 - bf2f(h));
    h = bf16bits(y3); aH[row*136 + lane + 96] = h; aL[row*136 + lane + 96] = bf16bits(y3 - bf2f(h));
}

// ============================================================
// Kernel W: pre-split the 6 weight matrices (0=wga 1=wpa 2=wgb 3=wpb 4=wog 5=wop)
// ============================================================
__global__ void __launch_bounds__(512, 1) prep_w_kernel(
    const float* __restrict__ wga, const float* __restrict__ wpa,
    const float* __restrict__ wgb, const float* __restrict__ wpb,
    const float* __restrict__ wog, const float* __restrict__ wop)
{
    const float* Ws[6] = {wga, wpa, wgb, wpb, wog, wop};
    const float* W = Ws[blockIdx.x];
    unsigned char* dst = g_wt + (size_t)blockIdx.x * 69632;
    #pragma unroll
    for (int it = 0; it < 8; it++) {
        int lin = threadIdx.x + it * 512;
        int r = lin >> 5, c4 = (lin & 31) << 2;
        float4 v = *(const float4*)(W + r * 128 + c4);
        uint2 hh, ll;
        split4(v, hh, ll);
        *(uint2*)(dst + r * TSTRIDE + c4 * 2) = hh;
        *(uint2*)(dst + 34816 + r * TSTRIDE + c4 * 2) = ll;
    }
}

// ============================================================
// Kernel P: LN(z) + 5 projections (pair-merged).  64 rows, 256 threads, 2 CTAs/SM.
// smem: A_hi 0, A_lo 17408, W0 34816 (36864: hi+lo), W1 71680 (36864) = 108544.
// Per phase: W0 = G tile, W1 = P tile (same K-half); both halves swept sequentially.
// z stage and pair epilogue stage overlay W1.
// ============================================================
#define PR_AHI 0u
#define PR_ALO 17408u
#define PR_W0  34816u
#define PR_W1  71680u
#define PR_SMEM 108544

__global__ void __launch_bounds__(256, 2) proj_kernel(
    const float* __restrict__ z, const float* __restrict__ gin, const float* __restrict__ bin,
    const float* __restrict__ bga, const float* __restrict__ bpa,
    const float* __restrict__ bgb, const float* __restrict__ bpb,
    const float* __restrict__ bog)
{
    extern __shared__ char smp[];
    const uint32_t sb = smem_u32(smp);
    const int tid = threadIdx.x, wid = tid >> 5, lane = tid & 31;

    const size_t m0 = (size_t)blockIdx.x * 64;
    const int b  = (int)(m0 >> 16);
    const int ii = (int)((m0 >> 8) & 255);
    const int k0 = (int)(m0 & 255);

    // async prefetch: z tile -> W1 stage [64][128] f32, and wga.h0 -> W0
    {
        const float* zsrc = z + m0 * 128;
        #pragma unroll
        for (int it = 0; it < 8; it++) {
            int lin = tid + it * 256;          // 0..2047 16B chunks
            int r = lin >> 5, c = lin & 31;
            cp16(sb + PR_W1 + (uint32_t)r * 512u + (uint32_t)c * 16u, zsrc + r * 128 + c * 4);
        }
        cp_commit();
    }
    load_w_half(sb + PR_W0, 0, 0);
    cp_wait0(); __syncthreads();

    {   // LN rows (from smem stage) -> split A tiles (8 rows per warp)
        const float* zs = (const float*)(smp + PR_W1);
        const float g0 = gin[lane], g1 = gin[lane+32], g2 = gin[lane+64], g3 = gin[lane+96];
        const float c0 = bin[lane], c1 = bin[lane+32], c2 = bin[lane+64], c3 = bin[lane+96];
        #pragma unroll
        for (int r = 0; r < 8; r++) {
            int row = wid * 8 + r;
            ln_row(smp, PR_AHI, PR_ALO, row, lane, zs + row * 128,
                   g0, g1, g2, g3, c0, c1, c2, c3);
        }
    }
    __syncthreads();        // z stage consumed
    load_w_half(sb + PR_W1, 1, 0);   // wpa.h0
    cp_wait0(); __syncthreads();

    const int m0w = (wid >> 2) * 32, n0w = (wid & 3) * 32;
    const uint32_t aH0 = sb + PR_AHI + (uint32_t)m0w * TSTRIDE;
    const uint32_t aL0 = sb + PR_ALO + (uint32_t)m0w * TSTRIDE;
    const uint32_t w0n = sb + PR_W0 + (uint32_t)n0w * HSTRIDE;
    const uint32_t w1n = sb + PR_W1 + (uint32_t)n0w * HSTRIDE;

    // ---- two gated-pair phases (entry invariant: W0 = G.h0, W1 = P.h0, no cp pending) ----
    for (int ph = 0; ph < 2; ph++) {
        const int gmat = ph ? 2 : 0, pmat = ph ? 3 : 1;
        const float* bg = ph ? bgb : bga;
        const float* bp = ph ? bpb : bpa;

        float accG[2][4][4] = {}, accP[2][4][4] = {};

        gemm_pair(accG, accP, aH0, aL0, w0n, w0n + 18432u, w1n, w1n + 18432u, lane);
        __syncthreads();
        load_w_half(sb + PR_W0, gmat, 1);      // G.h1
        load_w_half(sb + PR_W1, pmat, 1);      // P.h1
        cp_wait0(); __syncthreads();
        gemm_pair(accG, accP, aH0 + 128u, aL0 + 128u, w0n, w0n + 18432u, w1n, w1n + 18432u, lane);
        __syncthreads();

        // prefetch next phase G.h0 (or wog.h0) into W0 — overlaps epilogue
        load_w_half(sb + PR_W0, ph ? 4 : 2, 0);

        // stage transposed into W1: stH/stL [d 128][m 72] bf16
        uint16_t* stH = (uint16_t*)(smp + PR_W1);
        uint16_t* stL = (uint16_t*)(smp + PR_W1 + 18432u);
        #pragma unroll
        for (int mt = 0; mt < 2; mt++)
            #pragma unroll
            for (int q = 0; q < 4; q++) {
                int n = n0w + q * 8 + 2 * (lane & 3);
                float2 bg2 = *(const float2*)(bg + n);
                float2 bp2 = *(const float2*)(bp + n);
                #pragma unroll
                for (int rh = 0; rh < 2; rh++) {
                    int m = m0w + mt * 16 + (lane >> 2) + rh * 8;
                    float v0 = sigmoidf_(accG[mt][q][rh*2]   + bg2.x) * (accP[mt][q][rh*2]   + bp2.x);
                    float v1 = sigmoidf_(accG[mt][q][rh*2+1] + bg2.y) * (accP[mt][q][rh*2+1] + bp2.y);
                    uint16_t h0 = bf16bits(v0), h1 = bf16bits(v1);
                    stH[n * 72 + m]       = h0;  stL[n * 72 + m]       = bf16bits(v0 - bf2f(h0));
                    stH[(n + 1) * 72 + m] = h1;  stL[(n + 1) * 72 + m] = bf16bits(v1 - bf2f(h1));
                }
            }
        __syncthreads();

        __nv_bfloat16* dH = ph ? g_bt_hi : g_at_hi;
        __nv_bfloat16* dL = ph ? g_bt_lo : g_at_lo;
        #pragma unroll
        for (int it = 0; it < 8; it++) {
            int lin = tid + it * 256;               // 0..2047
            int hl  = lin >> 10;
            int idx = lin & 1023;
            int d = idx >> 3, m8 = (idx & 7) << 3;
            uint4 v = *(const uint4*)(smp + PR_W1 + (uint32_t)hl * 18432u + d * HSTRIDE + m8 * 2);
            __nv_bfloat16* dst = hl ? dL : dH;
            *(uint4*)(dst + ((size_t)(b * 128 + d)) * 65536 + (size_t)ii * 256 + k0 + m8) = v;
        }
        __syncthreads();                            // stage consumed
        // load next P.h0 (or wog.h1) into W1
        load_w_half(sb + PR_W1, ph ? 4 : 3, ph ? 1 : 0);
        cp_wait0(); __syncthreads();
    }

    // ---- gate phase (W0 = wog.h0, W1 = wog.h1; both resident, no mid-sync) ----
    float acc[2][4][4] = {};
    gemm32<TSTRIDE, HSTRIDE>(acc, aH0, aL0, w0n, w0n + 18432u, lane);
    gemm32<TSTRIDE, HSTRIDE>(acc, aH0 + 128u, aL0 + 128u, w1n, w1n + 18432u, lane);

    #pragma unroll
    for (int mt = 0; mt < 2; mt++)
        #pragma unroll
        for (int q = 0; q < 4; q++) {
            int n = n0w + q * 8 + 2 * (lane & 3);
            float2 bo2 = *(const float2*)(bog + n);
            #pragma unroll
            for (int rh = 0; rh < 2; rh++) {
                int m = m0w + mt * 16 + (lane >> 2) + rh * 8;
                __half2 o = __floats2half2_rn(sigmoidf_(acc[mt][q][rh*2]   + bo2.x),
                                              sigmoidf_(acc[mt][q][rh*2+1] + bo2.y));
                *(__half2*)(g_gate + (m0 + m) * 128 + n) = o;
            }
        }
}

// ============================================================
// Kernel T: triangle einsum. C tile 64x128, 256 threads (8 warps), 2 CTAs/SM.
// K = 256 in 4 chunks of 64, double-buffered (2 x 55296 = 110592 B).
// grid.x = 4096: bd = bx>>3, i0 = ((bx>>1)&3)*64, j0 = (bx&1)*128
// ============================================================
#define TR_BUFSZ 55296u
#define TR_SMEM  110592

__device__ __forceinline__ void tri_load_chunk(uint32_t bufBase, size_t base,
                                               int i0, int j0, int kc)
{
    #pragma unroll
    for (int it = 0; it < 12; it++) {
        int lin = threadIdx.x + it * 256;          // 0..3071
        if (lin < 1024) {                          // A: 64 rows, hi/lo
            int plane = lin >> 9, idx = lin & 511;
            int r = idx >> 3, c = idx & 7;
            const __nv_bfloat16* s = plane ? g_at_lo : g_at_hi;
            cp16(bufBase + (uint32_t)plane * 9216u + (uint32_t)r * HSTRIDE + (uint32_t)c * 16u,
                 s + base + (size_t)(i0 + r) * 256 + kc * 64 + c * 8);
        } else {                                   // B: 128 rows, hi/lo
            int l2 = lin - 1024;
            int plane = l2 >> 10, idx = l2 & 1023;
            int r = idx >> 3, c = idx & 7;
            const __nv_bfloat16* s = plane ? g_bt_lo : g_bt_hi;
            cp16(bufBase + 18432u + (uint32_t)plane * 18432u + (uint32_t)r * HSTRIDE + (uint32_t)c * 16u,
                 s + base + (size_t)(j0 + r) * 256 + kc * 64 + c * 8);
        }
    }
    cp_commit();
}

__global__ void __launch_bounds__(256, 2) tri_kernel()
{
    extern __shared__ char smp[];
    const uint32_t sb = smem_u32(smp);
    const int tid = threadIdx.x, wid = tid >> 5, lane = tid & 31;
    const int bx = blockIdx.x;
    const int bd = bx >> 3;
    const int i0 = ((bx >> 1) & 3) * 64;
    const int j0 = (bx & 1) * 128;
    const size_t base = (size_t)bd * 65536;

    const int m0w = (wid >> 2) * 32, n0w = (wid & 3) * 32;
    float acc[2][4][4] = {};

    tri_load_chunk(sb, base, i0, j0, 0);
    #pragma unroll
    for (int kc = 0; kc < 4; kc++) {
        cp_wait0(); __syncthreads();
        if (kc < 3) tri_load_chunk(sb + ((kc + 1) & 1) * TR_BUFSZ, base, i0, j0, kc + 1);
        const uint32_t bf = sb + (kc & 1) * TR_BUFSZ;
        gemm32<HSTRIDE, HSTRIDE>(acc,
            bf + (uint32_t)m0w * HSTRIDE, bf + 9216u + (uint32_t)m0w * HSTRIDE,
            bf + 18432u + (uint32_t)n0w * HSTRIDE, bf + 36864u + (uint32_t)n0w * HSTRIDE, lane);
    }

    #pragma unroll
    for (int mt = 0; mt < 2; mt++)
        #pragma unroll
        for (int q = 0; q < 4; q++) {
            int n = n0w + q * 8 + 2 * (lane & 3);
            #pragma unroll
            for (int rh = 0; rh < 2; rh++) {
                int m = m0w + mt * 16 + (lane >> 2) + rh * 8;
                __half2 o = __floats2half2_rn(acc[mt][q][rh*2], acc[mt][q][rh*2+1]);
                *(__half2*)(g_ot + base + (size_t)(i0 + m) * 256 + j0 + n) = o;
            }
        }
}

// ============================================================
// Kernel F: async gather + column-LN + wop + gate.  64 p-rows, 256 threads, 3 CTAs/SM.
// smem: A_hi 0, A_lo 17408; S fp16 [128 d][72] @34816 (18432 B, dead after LN);
//       W halves overlay S @34816 (36864).  Total 71680.
// grid.x = 4096: b = bx>>10, p0 = (bx&1023)*64
// ============================================================
#define FN_AHI 0u
#define FN_ALO 17408u
#define FN_S   34816u
#define FN_W   34816u
#define FN_SMEM 71680

__global__ void __launch_bounds__(256, 3) final_kernel(
    const float* __restrict__ gout, const float* __restrict__ bout,
    const float* __restrict__ bop, float* __restrict__ outp)
{
    extern __shared__ char smp[];
    const uint32_t sb = smem_u32(smp);
    const int tid = threadIdx.x, wid = tid >> 5, lane = tid & 31;
    const int b  = blockIdx.x >> 10;
    const int p0 = (blockIdx.x & 1023) * 64;

    // async raw gather: S[d][p] <- g_ot[b][d][p0 .. p0+63] fp16 (d-major, coalesced)
    {
        const __half* src = g_ot + (size_t)b * 128 * 65536 + p0;
        #pragma unroll
        for (int it = 0; it < 4; it++) {
            int lin = tid + it * 256;              // 0..1023 16B chunks
            int d = lin >> 3, c = lin & 7;
            cp16(sb + FN_S + (uint32_t)d * 144u + (uint32_t)c * 16u,
                 src + (size_t)d * 65536 + c * 8);
        }
        cp_commit();
    }
    cp_wait0(); __syncthreads();

    // column LN: warp w owns p = 8w..8w+7; 4 lanes per column (part = lane&3),
    // each lane covers d = part*32 + ((i + 2*part)&31).
    {
        const __half* S = (const __half*)(smp + FN_S);
        const int c  = lane >> 2, part = lane & 3;
        const int p  = wid * 8 + c;
        float s1 = 0.f;
        #pragma unroll
        for (int i = 0; i < 32; i++) {
            int d = part * 32 + ((i + 2 * part) & 31);
            s1 += __half2float(S[d * 72 + p]);
        }
        s1 += __shfl_xor_sync(0xffffffffu, s1, 1);
        s1 += __shfl_xor_sync(0xffffffffu, s1, 2);
        const float mean = s1 * (1.0f / 128.0f);
        float s2 = 0.f;
        #pragma unroll
        for (int i = 0; i < 32; i++) {
            int d = part * 32 + ((i + 2 * part) & 31);
            float v = __half2float(S[d * 72 + p]) - mean;
            s2 += v * v;
        }
        s2 += __shfl_xor_sync(0xffffffffu, s2, 1);
        s2 += __shfl_xor_sync(0xffffffffu, s2, 2);
        const float inv = rsqrtf(s2 * (1.0f / 128.0f) + 1e-5f);
        uint16_t* aH = (uint16_t*)(smp + FN_AHI);
        uint16_t* aL = (uint16_t*)(smp + FN_ALO);
        #pragma unroll
        for (int i = 0; i < 32; i++) {
            int d = part * 32 + ((i + 2 * part) & 31);
            float y = (__half2float(S[d * 72 + p]) - mean) * inv * gout[d] + bout[d];
            uint16_t h = bf16bits(y);
            aH[p * 136 + d] = h;
            aL[p * 136 + d] = bf16bits(y - bf2f(h));
        }
    }
    __syncthreads();            // S fully consumed before W overlays it

    const int m0w = (wid >> 2) * 32, n0w = (wid & 3) * 32;
    const uint32_t aH0 = sb + FN_AHI + (uint32_t)m0w * TSTRIDE;
    const uint32_t aL0 = sb + FN_ALO + (uint32_t)m0w * TSTRIDE;
    const uint32_t wn  = sb + FN_W + (uint32_t)n0w * HSTRIDE;

    float acc[2][4][4] = {};
    load_w_half(sb + FN_W, 5, 0);
    cp_wait0(); __syncthreads();
    gemm32<TSTRIDE, HSTRIDE>(acc, aH0, aL0, wn, wn + 18432u, lane);
    __syncthreads();
    load_w_half(sb + FN_W, 5, 1);
    cp_wait0(); __syncthreads();
    gemm32<TSTRIDE, HSTRIDE>(acc, aH0 + 128u, aL0 + 128u, wn, wn + 18432u, lane);

    #pragma unroll
    for (int mt = 0; mt < 2; mt++)
        #pragma unroll
        for (int q = 0; q < 4; q++) {
            int n = n0w + q * 8 + 2 * (lane & 3);
            float2 bo2 = *(const float2*)(bop + n);
            #pragma unroll
            for (int rh = 0; rh < 2; rh++) {
                int m = m0w + mt * 16 + (lane >> 2) + rh * 8;
                size_t gi = ((size_t)b * 65536 + p0 + m) * 128 + n;
                float2 g = __half22float2(*(const __half2*)(g_gate + gi));
                float2 o;
                o.x = g.x * (acc[mt][q][rh*2]   + bo2.x);
                o.y = g.y * (acc[mt][q][rh*2+1] + bo2.y);
                *(float2*)(outp + gi) = o;
            }
        }
}

// ============================================================
// launch
// ============================================================
extern "C" void kernel_launch(void* const* d_in, const int* in_sizes, int n_in,
                              void* d_out, int out_size)
{
    const float* z    = (const float*)d_in[0];
    const float* gin  = (const float*)d_in[1];
    const float* bin  = (const float*)d_in[2];
    const float* wpa  = (const float*)d_in[3];
    const float* bpa  = (const float*)d_in[4];
    const float* wga  = (const float*)d_in[5];
    const float* bga  = (const float*)d_in[6];
    const float* wpb  = (const float*)d_in[7];
    const float* bpb  = (const float*)d_in[8];
    const float* wgb  = (const float*)d_in[9];
    const float* bgb  = (const float*)d_in[10];
    const float* gout = (const float*)d_in[11];
    const float* bout = (const float*)d_in[12];
    const float* wop  = (const float*)d_in[13];
    const float* bop  = (const float*)d_in[14];
    const float* wog  = (const float*)d_in[15];
    const float* bog  = (const float*)d_in[16];
    float* outp = (float*)d_out;

    cudaFuncSetAttribute(proj_kernel,  cudaFuncAttributeMaxDynamicSharedMemorySize, PR_SMEM);
    cudaFuncSetAttribute(tri_kernel,   cudaFuncAttributeMaxDynamicSharedMemorySize, TR_SMEM);
    cudaFuncSetAttribute(final_kernel, cudaFuncAttributeMaxDynamicSharedMemorySize, FN_SMEM);

    prep_w_kernel<<<6, 512>>>(wga, wpa, wgb, wpb, wog, wop);
    proj_kernel<<<4096, 256, PR_SMEM>>>(z, gin, bin, bga, bpa, bgb, bpb, bog);
    tri_kernel<<<4096, 256, TR_SMEM>>>();
    final_kernel<<<4096, 256, FN_SMEM>>>(gout, bout, bop, outp);
}

// round 14
// speedup vs baseline: 1.0172x; 1.0172x over previous
#include <cuda_runtime.h>
#include <cuda_bf16.h>
#include <cuda_fp16.h>
#include <stdint.h>

#define ELEMS ((size_t)4*256*256*128)   // 33.5M

// ---------------- scratch ----------------
__device__ __align__(16) __nv_bfloat16 g_at_hi[ELEMS];
__device__ __align__(16) __nv_bfloat16 g_at_lo[ELEMS];
__device__ __align__(16) __nv_bfloat16 g_bt_hi[ELEMS];
__device__ __align__(16) __nv_bfloat16 g_bt_lo[ELEMS];
__device__ __align__(16) __half g_gate[ELEMS];   // fp16: sigmoid in (0,1)
__device__ __align__(16) __half g_ot[ELEMS];     // fp16: LN-normalized downstream
// pre-split weight tile images: 6 mats x (hi 34816 B + lo 34816 B), 272 B row stride
__device__ __align__(16) unsigned char g_wt[6 * 69632];

// ---------------- helpers ----------------
__device__ __forceinline__ uint32_t smem_u32(const void* p){
    uint32_t a;
    asm("{ .reg .u64 t; cvta.to.shared.u64 t, %1; cvt.u32.u64 %0, t; }" : "=r"(a) : "l"(p));
    return a;
}
__device__ __forceinline__ void ldsm_x4(uint32_t* r, uint32_t a){
    asm volatile("ldmatrix.sync.aligned.m8n8.x4.shared.b16 {%0,%1,%2,%3}, [%4];"
        : "=r"(r[0]), "=r"(r[1]), "=r"(r[2]), "=r"(r[3]) : "r"(a));
}
__device__ __forceinline__ void mma16816(float* c, const uint32_t* a, const uint32_t* b){
    asm volatile("mma.sync.aligned.m16n8k16.row.col.f32.bf16.bf16.f32 "
        "{%0,%1,%2,%3}, {%4,%5,%6,%7}, {%8,%9}, {%0,%1,%2,%3};"
        : "+f"(c[0]), "+f"(c[1]), "+f"(c[2]), "+f"(c[3])
        : "r"(a[0]), "r"(a[1]), "r"(a[2]), "r"(a[3]), "r"(b[0]), "r"(b[1]));
}
__device__ __forceinline__ void cp16(uint32_t dst, const void* src){
    asm volatile("cp.async.cg.shared.global [%0], [%1], 16;" :: "r"(dst), "l"(src));
}
__device__ __forceinline__ void cp_commit(){
    asm volatile("cp.async.commit_group;" ::: "memory");
}
__device__ __forceinline__ void cp_wait0(){
    asm volatile("cp.async.wait_group 0;" ::: "memory");
}
__device__ __forceinline__ float sigmoidf_(float x){ return 1.0f / (1.0f + __expf(-x)); }
__device__ __forceinline__ uint16_t bf16bits(float v){
    __nv_bfloat16 h = __float2bfloat16(v);
    return *reinterpret_cast<uint16_t*>(&h);
}
__device__ __forceinline__ float bf2f(uint16_t u){
    __nv_bfloat16 h = *reinterpret_cast<__nv_bfloat16*>(&u);
    return __bfloat162float(h);
}
__device__ __forceinline__ void split4(float4 v, uint2& hh, uint2& ll){
    uint16_t h0=bf16bits(v.x), h1=bf16bits(v.y), h2=bf16bits(v.z), h3=bf16bits(v.w);
    uint16_t l0=bf16bits(v.x-bf2f(h0)), l1=bf16bits(v.y-bf2f(h1)),
             l2=bf16bits(v.z-bf2f(h2)), l3=bf16bits(v.w-bf2f(h3));
    hh.x = (uint32_t)h0 | ((uint32_t)h1<<16); hh.y = (uint32_t)h2 | ((uint32_t)h3<<16);
    ll.x = (uint32_t)l0 | ((uint32_t)l1<<16); ll.y = (uint32_t)l2 | ((uint32_t)l3<<16);
}

#define TSTRIDE 272u   // full-K (128) bf16 tile row stride in bytes
#define HSTRIDE 144u   // half-K (64)  bf16 tile row stride in bytes

// 32x(NTC*32) warp-tile split GEMM over 64 K (4 ksteps). acc[2][NTC*4][4].
template<int NTC, int SA, int SB>
__device__ __forceinline__ void gemm_nt(float (&acc)[2][NTC*4][4],
    uint32_t aHi, uint32_t aLo, uint32_t bHi, uint32_t bLo, int lane)
{
    const uint32_t aOff = (uint32_t)(lane & 15) * SA + (uint32_t)((lane >> 4) << 4);
    const uint32_t bOff = (uint32_t)(((lane >> 4) << 3) + (lane & 7)) * SB
                        + (uint32_t)(((lane >> 3) & 1) << 4);
    #pragma unroll
    for (int ks = 0; ks < 4; ks++) {
        const uint32_t ka = aOff + (uint32_t)ks * 32u;
        const uint32_t kb = bOff + (uint32_t)ks * 32u;
        uint32_t ah[2][4], al[2][4];
        ldsm_x4(ah[0], aHi + ka);
        ldsm_x4(ah[1], aHi + 16u * SA + ka);
        ldsm_x4(al[0], aLo + ka);
        ldsm_x4(al[1], aLo + 16u * SA + ka);
        #pragma unroll
        for (int nc = 0; nc < NTC; nc++) {
            const uint32_t bn = (uint32_t)nc * 32u * SB + kb;
            uint32_t bb[2][4];
            ldsm_x4(bb[0], bHi + bn);
            ldsm_x4(bb[1], bHi + bn + 16u * SB);
            #pragma unroll
            for (int mt = 0; mt < 2; mt++)
                #pragma unroll
                for (int q = 0; q < 4; q++)
                    mma16816(acc[mt][nc*4+q], ah[mt], &bb[q >> 1][(q & 1) << 1]);
            #pragma unroll
            for (int mt = 0; mt < 2; mt++)
                #pragma unroll
                for (int q = 0; q < 4; q++)
                    mma16816(acc[mt][nc*4+q], al[mt], &bb[q >> 1][(q & 1) << 1]);
            ldsm_x4(bb[0], bLo + bn);
            ldsm_x4(bb[1], bLo + bn + 16u * SB);
            #pragma unroll
            for (int mt = 0; mt < 2; mt++)
                #pragma unroll
                for (int q = 0; q < 4; q++)
                    mma16816(acc[mt][nc*4+q], ah[mt], &bb[q >> 1][(q & 1) << 1]);
        }
    }
}

// async copy one half-K (64k) weight tile (hi + lo planes), 256-thread blocks
__device__ __forceinline__ void load_w_half(uint32_t dst, int mat, int half){
    const unsigned char* src = g_wt + (size_t)mat * 69632 + half * 128;
    #pragma unroll
    for (int it = 0; it < 8; it++) {
        int lin = threadIdx.x + it * 256;      // 0..2047
        int plane = lin >> 10, idx = lin & 1023;
        int r = idx >> 3, c = idx & 7;
        cp16(dst + (uint32_t)plane * 18432u + (uint32_t)r * HSTRIDE + (uint32_t)c * 16u,
             src + (size_t)plane * 34816 + (size_t)r * 272 + c * 16);
    }
    cp_commit();
}

// LN one row (128 cols) by a full warp; write split bf16 into A tile (272B stride).
__device__ __forceinline__ void ln_row(char* smp, uint32_t hiOff, uint32_t loOff,
    int row, int lane, const float* x,
    float g0, float g1, float g2, float g3,
    float c0, float c1, float c2, float c3)
{
    float v0 = x[lane], v1 = x[lane+32], v2 = x[lane+64], v3 = x[lane+96];
    float s = v0 + v1 + v2 + v3;
    #pragma unroll
    for (int o = 16; o > 0; o >>= 1) s += __shfl_xor_sync(0xffffffffu, s, o);
    float mean = s * (1.0f / 128.0f);
    float d0 = v0-mean, d1 = v1-mean, d2 = v2-mean, d3 = v3-mean;
    float q = d0*d0 + d1*d1 + d2*d2 + d3*d3;
    #pragma unroll
    for (int o = 16; o > 0; o >>= 1) q += __shfl_xor_sync(0xffffffffu, q, o);
    float inv = rsqrtf(q * (1.0f / 128.0f) + 1e-5f);
    float y0 = d0*inv*g0 + c0, y1 = d1*inv*g1 + c1;
    float y2 = d2*inv*g2 + c2, y3 = d3*inv*g3 + c3;
    uint16_t* aH = (uint16_t*)(smp + hiOff);
    uint16_t* aL = (uint16_t*)(smp + loOff);
    uint16_t h;
    h = bf16bits(y0); aH[row*136 + lane]      = h; aL[row*136 + lane]      = bf16bits(y0 - bf2f(h));
    h = bf16bits(y1); aH[row*136 + lane + 32] = h; aL[row*136 + lane + 32] = bf16bits(y1 - bf2f(h));
    h = bf16bits(y2); aH[row*136 + lane + 64] = h; aL[row*136 + lane + 64] = bf16bits(y2 - bf2f(h));
    h = bf16bits(y3); aH[row*136 + lane + 96] = h; aL[row*136 + lane + 96] = bf16bits(y3 - bf2f(h));
}

// ============================================================
// Kernel W: pre-split the 6 weight matrices (0=wga 1=wpa 2=wgb 3=wpb 4=wog 5=wop)
// ============================================================
__global__ void __launch_bounds__(512, 1) prep_w_kernel(
    const float* __restrict__ wga, const float* __restrict__ wpa,
    const float* __restrict__ wgb, const float* __restrict__ wpb,
    const float* __restrict__ wog, const float* __restrict__ wop)
{
    const float* Ws[6] = {wga, wpa, wgb, wpb, wog, wop};
    const float* W = Ws[blockIdx.x];
    unsigned char* dst = g_wt + (size_t)blockIdx.x * 69632;
    #pragma unroll
    for (int it = 0; it < 8; it++) {
        int lin = threadIdx.x + it * 512;
        int r = lin >> 5, c4 = (lin & 31) << 2;
        float4 v = *(const float4*)(W + r * 128 + c4);
        uint2 hh, ll;
        split4(v, hh, ll);
        *(uint2*)(dst + r * TSTRIDE + c4 * 2) = hh;
        *(uint2*)(dst + 34816 + r * TSTRIDE + c4 * 2) = ll;
    }
}

// ============================================================
// Kernel P: LN(z) + 5 projections.  64 rows, 256 threads (8 warps, 2m x 4n), 2 CTAs/SM.
// smem: A_hi 0, A_lo 17408, WBUF0 34816 (36864), WBUF1 71680 (36864) = 108544.
// (round-12 structure: z staged async; sequential G/P gemms.)
// ============================================================
#define PR_AHI 0u
#define PR_ALO 17408u
#define PR_WB0 34816u
#define PR_WB1 71680u
#define PR_SMEM 108544

__global__ void __launch_bounds__(256, 2) proj_kernel(
    const float* __restrict__ z, const float* __restrict__ gin, const float* __restrict__ bin,
    const float* __restrict__ bga, const float* __restrict__ bpa,
    const float* __restrict__ bgb, const float* __restrict__ bpb,
    const float* __restrict__ bog)
{
    extern __shared__ char smp[];
    const uint32_t sb = smem_u32(smp);
    const int tid = threadIdx.x, wid = tid >> 5, lane = tid & 31;

    const size_t m0 = (size_t)blockIdx.x * 64;
    const int b  = (int)(m0 >> 16);
    const int ii = (int)((m0 >> 8) & 255);
    const int k0 = (int)(m0 & 255);

    // async prefetch: z tile -> WB1 stage [64][128] f32, and wga.h0 -> WB0
    {
        const float* zsrc = z + m0 * 128;
        #pragma unroll
        for (int it = 0; it < 8; it++) {
            int lin = tid + it * 256;
            int r = lin >> 5, c = lin & 31;
            cp16(sb + PR_WB1 + (uint32_t)r * 512u + (uint32_t)c * 16u, zsrc + r * 128 + c * 4);
        }
        cp_commit();
    }
    load_w_half(sb + PR_WB0, 0, 0);
    cp_wait0(); __syncthreads();

    {   // LN rows (from smem stage) -> split A tiles (8 rows per warp)
        const float* zs = (const float*)(smp + PR_WB1);
        const float g0 = gin[lane], g1 = gin[lane+32], g2 = gin[lane+64], g3 = gin[lane+96];
        const float c0 = bin[lane], c1 = bin[lane+32], c2 = bin[lane+64], c3 = bin[lane+96];
        #pragma unroll
        for (int r = 0; r < 8; r++) {
            int row = wid * 8 + r;
            ln_row(smp, PR_AHI, PR_ALO, row, lane, zs + row * 128,
                   g0, g1, g2, g3, c0, c1, c2, c3);
        }
    }
    __syncthreads();        // z stage consumed before WB1 is overwritten

    const int m0w = (wid >> 2) * 32, n0w = (wid & 3) * 32;
    const uint32_t aH0 = sb + PR_AHI + (uint32_t)m0w * TSTRIDE;
    const uint32_t aL0 = sb + PR_ALO + (uint32_t)m0w * TSTRIDE;
    const uint32_t b0n = sb + PR_WB0 + (uint32_t)n0w * HSTRIDE;
    const uint32_t b1n = sb + PR_WB1 + (uint32_t)n0w * HSTRIDE;

    // ---- two gated-pair phases (invariant at entry: WB0 = (gmat, h0), no cp pending) ----
    for (int ph = 0; ph < 2; ph++) {
        const int gmat = ph ? 2 : 0, pmat = ph ? 3 : 1;
        const float* bg = ph ? bgb : bga;
        const float* bp = ph ? bpb : bpa;

        float accG[2][4][4] = {}, accP[2][4][4] = {};

        load_w_half(sb + PR_WB1, gmat, 1);
        gemm_nt<1, TSTRIDE, HSTRIDE>(accG, aH0, aL0, b0n, b0n + 18432u, lane);
        cp_wait0(); __syncthreads();

        load_w_half(sb + PR_WB0, pmat, 0);
        gemm_nt<1, TSTRIDE, HSTRIDE>(accG, aH0 + 128u, aL0 + 128u, b1n, b1n + 18432u, lane);
        cp_wait0(); __syncthreads();

        load_w_half(sb + PR_WB1, pmat, 1);
        gemm_nt<1, TSTRIDE, HSTRIDE>(accP, aH0, aL0, b0n, b0n + 18432u, lane);
        cp_wait0(); __syncthreads();

        gemm_nt<1, TSTRIDE, HSTRIDE>(accP, aH0 + 128u, aL0 + 128u, b1n, b1n + 18432u, lane);
        __syncthreads();

        // stage transposed into WBUF1: stH/stL [d 128][m 72] bf16
        uint16_t* stH = (uint16_t*)(smp + PR_WB1);
        uint16_t* stL = (uint16_t*)(smp + PR_WB1 + 18432u);
        #pragma unroll
        for (int mt = 0; mt < 2; mt++)
            #pragma unroll
            for (int q = 0; q < 4; q++) {
                int n = n0w + q * 8 + 2 * (lane & 3);
                float2 bg2 = *(const float2*)(bg + n);
                float2 bp2 = *(const float2*)(bp + n);
                #pragma unroll
                for (int rh = 0; rh < 2; rh++) {
                    int m = m0w + mt * 16 + (lane >> 2) + rh * 8;
                    float v0 = sigmoidf_(accG[mt][q][rh*2]   + bg2.x) * (accP[mt][q][rh*2]   + bp2.x);
                    float v1 = sigmoidf_(accG[mt][q][rh*2+1] + bg2.y) * (accP[mt][q][rh*2+1] + bp2.y);
                    uint16_t h0 = bf16bits(v0), h1 = bf16bits(v1);
                    stH[n * 72 + m]       = h0;  stL[n * 72 + m]       = bf16bits(v0 - bf2f(h0));
                    stH[(n + 1) * 72 + m] = h1;  stL[(n + 1) * 72 + m] = bf16bits(v1 - bf2f(h1));
                }
            }
        __syncthreads();

        load_w_half(sb + PR_WB0, ph ? 4 : 2, 0);    // next phase h0 — overlaps the store below

        __nv_bfloat16* dH = ph ? g_bt_hi : g_at_hi;
        __nv_bfloat16* dL = ph ? g_bt_lo : g_at_lo;
        #pragma unroll
        for (int it = 0; it < 8; it++) {
            int lin = tid + it * 256;               // 0..2047
            int hl  = lin >> 10;
            int idx = lin & 1023;
            int d = idx >> 3, m8 = (idx & 7) << 3;
            uint4 v = *(const uint4*)(smp + PR_WB1 + (uint32_t)hl * 18432u + d * HSTRIDE + m8 * 2);
            __nv_bfloat16* dst = hl ? dL : dH;
            *(uint4*)(dst + ((size_t)(b * 128 + d)) * 65536 + (size_t)ii * 256 + k0 + m8) = v;
        }
        cp_wait0(); __syncthreads();
    }

    // ---- gate phase (WB0 = wog h0) ----
    float acc[2][4][4] = {};
    load_w_half(sb + PR_WB1, 4, 1);
    gemm_nt<1, TSTRIDE, HSTRIDE>(acc, aH0, aL0, b0n, b0n + 18432u, lane);
    cp_wait0(); __syncthreads();
    gemm_nt<1, TSTRIDE, HSTRIDE>(acc, aH0 + 128u, aL0 + 128u, b1n, b1n + 18432u, lane);

    #pragma unroll
    for (int mt = 0; mt < 2; mt++)
        #pragma unroll
        for (int q = 0; q < 4; q++) {
            int n = n0w + q * 8 + 2 * (lane & 3);
            float2 bo2 = *(const float2*)(bog + n);
            #pragma unroll
            for (int rh = 0; rh < 2; rh++) {
                int m = m0w + mt * 16 + (lane >> 2) + rh * 8;
                __half2 o = __floats2half2_rn(sigmoidf_(acc[mt][q][rh*2]   + bo2.x),
                                              sigmoidf_(acc[mt][q][rh*2+1] + bo2.y));
                *(__half2*)(g_gate + (m0 + m) * 128 + n) = o;
            }
        }
}

// ============================================================
// Kernel T: triangle einsum. C tile 128x256 (full j), 512 threads (16 warps 4m x 4n),
// 1 CTA/SM.  K = 256 in 4 chunks of 64, double-buffered (2 x 110592 = 221184 B).
// Chunk layout: A_hi 0 (18432), A_lo 18432, B_hi 36864 (36864), B_lo 73728.
// grid.x = 1024: bd = bx>>1, i0 = (bx&1)*128.
// Halves A/B re-read traffic vs 64x128 tiles.
// ============================================================
#define TR_CHSZ 110592u
#define TR_SMEM 221184

__device__ __forceinline__ void tri_load_chunk(uint32_t bufBase, size_t base,
                                               int i0, int kc)
{
    #pragma unroll
    for (int it = 0; it < 12; it++) {
        int lin = threadIdx.x + it * 512;          // 0..6143
        if (lin < 2048) {                          // A: 128 rows, hi/lo
            int plane = lin >> 10, idx = lin & 1023;
            int r = idx >> 3, c = idx & 7;
            const __nv_bfloat16* s = plane ? g_at_lo : g_at_hi;
            cp16(bufBase + (uint32_t)plane * 18432u + (uint32_t)r * HSTRIDE + (uint32_t)c * 16u,
                 s + base + (size_t)(i0 + r) * 256 + kc * 64 + c * 8);
        } else {                                   // B: 256 rows, hi/lo
            int l2 = lin - 2048;                   // 0..4095
            int plane = l2 >> 11, idx = l2 & 2047;
            int r = idx >> 3, c = idx & 7;
            const __nv_bfloat16* s = plane ? g_bt_lo : g_bt_hi;
            cp16(bufBase + 36864u + (uint32_t)plane * 36864u + (uint32_t)r * HSTRIDE + (uint32_t)c * 16u,
                 s + base + (size_t)r * 256 + kc * 64 + c * 8);
        }
    }
    cp_commit();
}

__global__ void __launch_bounds__(512, 1) tri_kernel()
{
    extern __shared__ char smp[];
    const uint32_t sb = smem_u32(smp);
    const int tid = threadIdx.x, wid = tid >> 5, lane = tid & 31;
    const int bx = blockIdx.x;
    const int bd = bx >> 1;
    const int i0 = (bx & 1) * 128;
    const size_t base = (size_t)bd * 65536;

    const int m0w = (wid >> 2) * 32, n0w = (wid & 3) * 64;
    float acc[2][8][4] = {};

    tri_load_chunk(sb, base, i0, 0);
    #pragma unroll
    for (int kc = 0; kc < 4; kc++) {
        cp_wait0(); __syncthreads();
        if (kc < 3) tri_load_chunk(sb + ((kc + 1) & 1) * TR_CHSZ, base, i0, kc + 1);
        const uint32_t bf = sb + (kc & 1) * TR_CHSZ;
        gemm_nt<2, HSTRIDE, HSTRIDE>(acc,
            bf + (uint32_t)m0w * HSTRIDE,            bf + 18432u + (uint32_t)m0w * HSTRIDE,
            bf + 36864u + (uint32_t)n0w * HSTRIDE,   bf + 73728u + (uint32_t)n0w * HSTRIDE, lane);
    }

    #pragma unroll
    for (int mt = 0; mt < 2; mt++)
        #pragma unroll
        for (int nc = 0; nc < 2; nc++)
            #pragma unroll
            for (int q = 0; q < 4; q++) {
                int n = n0w + nc * 32 + q * 8 + 2 * (lane & 3);
                #pragma unroll
                for (int rh = 0; rh < 2; rh++) {
                    int m = m0w + mt * 16 + (lane >> 2) + rh * 8;
                    __half2 o = __floats2half2_rn(acc[mt][nc*4+q][rh*2], acc[mt][nc*4+q][rh*2+1]);
                    *(__half2*)(g_ot + base + (size_t)(i0 + m) * 256 + n) = o;
                }
            }
}

// ============================================================
// Kernel F: async gather + column-LN + wop + gate.  64 p-rows, 256 threads, 3 CTAs/SM.
// smem: A_hi 0, A_lo 17408; S fp16 [128 d][72] @34816 (18432 B, dead after LN);
//       W halves overlay S @34816 (36864).  Total 71680.
// grid.x = 4096: b = bx>>10, p0 = (bx&1023)*64
// ============================================================
#define FN_AHI 0u
#define FN_ALO 17408u
#define FN_S   34816u
#define FN_W   34816u
#define FN_SMEM 71680

__global__ void __launch_bounds__(256, 3) final_kernel(
    const float* __restrict__ gout, const float* __restrict__ bout,
    const float* __restrict__ bop, float* __restrict__ outp)
{
    extern __shared__ char smp[];
    const uint32_t sb = smem_u32(smp);
    const int tid = threadIdx.x, wid = tid >> 5, lane = tid & 31;
    const int b  = blockIdx.x >> 10;
    const int p0 = (blockIdx.x & 1023) * 64;

    // async raw gather: S[d][p] <- g_ot[b][d][p0 .. p0+63] fp16 (d-major, coalesced)
    {
        const __half* src = g_ot + (size_t)b * 128 * 65536 + p0;
        #pragma unroll
        for (int it = 0; it < 4; it++) {
            int lin = tid + it * 256;              // 0..1023 16B chunks
            int d = lin >> 3, c = lin & 7;
            cp16(sb + FN_S + (uint32_t)d * 144u + (uint32_t)c * 16u,
                 src + (size_t)d * 65536 + c * 8);
        }
        cp_commit();
    }
    cp_wait0(); __syncthreads();

    // column LN: warp w owns p = 8w..8w+7; 4 lanes per column (part = lane&3),
    // each lane covers d = part*32 + ((i + 2*part)&31).
    {
        const __half* S = (const __half*)(smp + FN_S);
        const int c  = lane >> 2, part = lane & 3;
        const int p  = wid * 8 + c;
        float s1 = 0.f;
        #pragma unroll
        for (int i = 0; i < 32; i++) {
            int d = part * 32 + ((i + 2 * part) & 31);
            s1 += __half2float(S[d * 72 + p]);
        }
        s1 += __shfl_xor_sync(0xffffffffu, s1, 1);
        s1 += __shfl_xor_sync(0xffffffffu, s1, 2);
        const float mean = s1 * (1.0f / 128.0f);
        float s2 = 0.f;
        #pragma unroll
        for (int i = 0; i < 32; i++) {
            int d = part * 32 + ((i + 2 * part) & 31);
            float v = __half2float(S[d * 72 + p]) - mean;
            s2 += v * v;
        }
        s2 += __shfl_xor_sync(0xffffffffu, s2, 1);
        s2 += __shfl_xor_sync(0xffffffffu, s2, 2);
        const float inv = rsqrtf(s2 * (1.0f / 128.0f) + 1e-5f);
        uint16_t* aH = (uint16_t*)(smp + FN_AHI);
        uint16_t* aL = (uint16_t*)(smp + FN_ALO);
        #pragma unroll
        for (int i = 0; i < 32; i++) {
            int d = part * 32 + ((i + 2 * part) & 31);
            float y = (__half2float(S[d * 72 + p]) - mean) * inv * gout[d] + bout[d];
            uint16_t h = bf16bits(y);
            aH[p * 136 + d] = h;
            aL[p * 136 + d] = bf16bits(y - bf2f(h));
        }
    }
    __syncthreads();            // S fully consumed before W overlays it

    const int m0w = (wid >> 2) * 32, n0w = (wid & 3) * 32;
    const uint32_t aH0 = sb + FN_AHI + (uint32_t)m0w * TSTRIDE;
    const uint32_t aL0 = sb + FN_ALO + (uint32_t)m0w * TSTRIDE;
    const uint32_t wn  = sb + FN_W + (uint32_t)n0w * HSTRIDE;

    float acc[2][4][4] = {};
    load_w_half(sb + FN_W, 5, 0);
    cp_wait0(); __syncthreads();
    gemm_nt<1, TSTRIDE, HSTRIDE>(acc, aH0, aL0, wn, wn + 18432u, lane);
    __syncthreads();
    load_w_half(sb + FN_W, 5, 1);
    cp_wait0(); __syncthreads();
    gemm_nt<1, TSTRIDE, HSTRIDE>(acc, aH0 + 128u, aL0 + 128u, wn, wn + 18432u, lane);

    #pragma unroll
    for (int mt = 0; mt < 2; mt++)
        #pragma unroll
        for (int q = 0; q < 4; q++) {
            int n = n0w + q * 8 + 2 * (lane & 3);
            float2 bo2 = *(const float2*)(bop + n);
            #pragma unroll
            for (int rh = 0; rh < 2; rh++) {
                int m = m0w + mt * 16 + (lane >> 2) + rh * 8;
                size_t gi = ((size_t)b * 65536 + p0 + m) * 128 + n;
                float2 g = __half22float2(*(const __half2*)(g_gate + gi));
                float2 o;
                o.x = g.x * (acc[mt][q][rh*2]   + bo2.x);
                o.y = g.y * (acc[mt][q][rh*2+1] + bo2.y);
                *(float2*)(outp + gi) = o;
            }
        }
}

// ============================================================
// launch
// ============================================================
extern "C" void kernel_launch(void* const* d_in, const int* in_sizes, int n_in,
                              void* d_out, int out_size)
{
    const float* z    = (const float*)d_in[0];
    const float* gin  = (const float*)d_in[1];
    const float* bin  = (const float*)d_in[2];
    const float* wpa  = (const float*)d_in[3];
    const float* bpa  = (const float*)d_in[4];
    const float* wga  = (const float*)d_in[5];
    const float* bga  = (const float*)d_in[6];
    const float* wpb  = (const float*)d_in[7];
    const float* bpb  = (const float*)d_in[8];
    const float* wgb  = (const float*)d_in[9];
    const float* bgb  = (const float*)d_in[10];
    const float* gout = (const float*)d_in[11];
    const float* bout = (const float*)d_in[12];
    const float* wop  = (const float*)d_in[13];
    const float* bop  = (const float*)d_in[14];
    const float* wog  = (const float*)d_in[15];
    const float* bog  = (const float*)d_in[16];
    float* outp = (float*)d_out;

    cudaFuncSetAttribute(proj_kernel,  cudaFuncAttributeMaxDynamicSharedMemorySize, PR_SMEM);
    cudaFuncSetAttribute(tri_kernel,   cudaFuncAttributeMaxDynamicSharedMemorySize, TR_SMEM);
    cudaFuncSetAttribute(final_kernel, cudaFuncAttributeMaxDynamicSharedMemorySize, FN_SMEM);

    prep_w_kernel<<<6, 512>>>(wga, wpa, wgb, wpb, wog, wop);
    proj_kernel<<<4096, 256, PR_SMEM>>>(z, gin, bin, bga, bpa, bgb, bpb, bog);
    tri_kernel<<<1024, 512, TR_SMEM>>>();
    final_kernel<<<4096, 256, FN_SMEM>>>(gout, bout, bop, outp);
}

// round 15
// speedup vs baseline: 1.1598x; 1.1402x over previous
#include <cuda_runtime.h>
#include <cuda_bf16.h>
#include <cuda_fp16.h>
#include <stdint.h>

#define ELEMS ((size_t)4*256*256*128)   // 33.5M

// ---------------- scratch ----------------
__device__ __align__(16) __half g_at[ELEMS];     // fp16 gated projection a (b,d,i,k)
__device__ __align__(16) __half g_bt[ELEMS];     // fp16 gated projection b (b,d,j,k)
__device__ __align__(16) __half g_gate[ELEMS];   // fp16 sigmoid gate
__device__ __align__(16) __half g_ot[ELEMS];     // fp16 triangle result (b,d,i,j)
// pre-split weight tile images: 6 mats x (hi 34816 B + lo 34816 B), 272 B row stride
__device__ __align__(16) unsigned char g_wt[6 * 69632];

// ---------------- helpers ----------------
__device__ __forceinline__ uint32_t smem_u32(const void* p){
    uint32_t a;
    asm("{ .reg .u64 t; cvta.to.shared.u64 t, %1; cvt.u32.u64 %0, t; }" : "=r"(a) : "l"(p));
    return a;
}
__device__ __forceinline__ void ldsm_x4(uint32_t* r, uint32_t a){
    asm volatile("ldmatrix.sync.aligned.m8n8.x4.shared.b16 {%0,%1,%2,%3}, [%4];"
        : "=r"(r[0]), "=r"(r[1]), "=r"(r[2]), "=r"(r[3]) : "r"(a));
}
__device__ __forceinline__ void mma16816(float* c, const uint32_t* a, const uint32_t* b){
    asm volatile("mma.sync.aligned.m16n8k16.row.col.f32.bf16.bf16.f32 "
        "{%0,%1,%2,%3}, {%4,%5,%6,%7}, {%8,%9}, {%0,%1,%2,%3};"
        : "+f"(c[0]), "+f"(c[1]), "+f"(c[2]), "+f"(c[3])
        : "r"(a[0]), "r"(a[1]), "r"(a[2]), "r"(a[3]), "r"(b[0]), "r"(b[1]));
}
__device__ __forceinline__ void mma16816h(float* c, const uint32_t* a, const uint32_t* b){
    asm volatile("mma.sync.aligned.m16n8k16.row.col.f32.f16.f16.f32 "
        "{%0,%1,%2,%3}, {%4,%5,%6,%7}, {%8,%9}, {%0,%1,%2,%3};"
        : "+f"(c[0]), "+f"(c[1]), "+f"(c[2]), "+f"(c[3])
        : "r"(a[0]), "r"(a[1]), "r"(a[2]), "r"(a[3]), "r"(b[0]), "r"(b[1]));
}
__device__ __forceinline__ void cp16(uint32_t dst, const void* src){
    asm volatile("cp.async.cg.shared.global [%0], [%1], 16;" :: "r"(dst), "l"(src));
}
__device__ __forceinline__ void cp_commit(){
    asm volatile("cp.async.commit_group;" ::: "memory");
}
__device__ __forceinline__ void cp_wait0(){
    asm volatile("cp.async.wait_group 0;" ::: "memory");
}
__device__ __forceinline__ float sigmoidf_(float x){ return 1.0f / (1.0f + __expf(-x)); }
__device__ __forceinline__ uint16_t bf16bits(float v){
    __nv_bfloat16 h = __float2bfloat16(v);
    return *reinterpret_cast<uint16_t*>(&h);
}
__device__ __forceinline__ float bf2f(uint16_t u){
    __nv_bfloat16 h = *reinterpret_cast<__nv_bfloat16*>(&u);
    return __bfloat162float(h);
}
__device__ __forceinline__ void split4(float4 v, uint2& hh, uint2& ll){
    uint16_t h0=bf16bits(v.x), h1=bf16bits(v.y), h2=bf16bits(v.z), h3=bf16bits(v.w);
    uint16_t l0=bf16bits(v.x-bf2f(h0)), l1=bf16bits(v.y-bf2f(h1)),
             l2=bf16bits(v.z-bf2f(h2)), l3=bf16bits(v.w-bf2f(h3));
    hh.x = (uint32_t)h0 | ((uint32_t)h1<<16); hh.y = (uint32_t)h2 | ((uint32_t)h3<<16);
    ll.x = (uint32_t)l0 | ((uint32_t)l1<<16); ll.y = (uint32_t)l2 | ((uint32_t)l3<<16);
}

#define TSTRIDE 272u   // full-K (128) 16-bit tile row stride in bytes
#define HSTRIDE 144u   // half-K (64)  16-bit tile row stride in bytes

// 32x32 warp-tile split-bf16 GEMM over 64 K (4 ksteps). acc[2][4][4]. 3 terms.
template<int SA, int SB>
__device__ __forceinline__ void gemm32(float (&acc)[2][4][4],
    uint32_t aHi, uint32_t aLo, uint32_t bHi, uint32_t bLo, int lane)
{
    const uint32_t aOff = (uint32_t)(lane & 15) * SA + (uint32_t)((lane >> 4) << 4);
    const uint32_t bOff = (uint32_t)(((lane >> 4) << 3) + (lane & 7)) * SB
                        + (uint32_t)(((lane >> 3) & 1) << 4);
    #pragma unroll
    for (int ks = 0; ks < 4; ks++) {
        const uint32_t ka = aOff + (uint32_t)ks * 32u;
        const uint32_t kb = bOff + (uint32_t)ks * 32u;
        uint32_t ah[2][4], al[2][4], bb[2][4];
        ldsm_x4(ah[0], aHi + ka);
        ldsm_x4(ah[1], aHi + 16u * SA + ka);
        ldsm_x4(bb[0], bHi + kb);
        ldsm_x4(bb[1], bHi + 16u * SB + kb);
        #pragma unroll
        for (int mt = 0; mt < 2; mt++)
            #pragma unroll
            for (int q = 0; q < 4; q++)
                mma16816(acc[mt][q], ah[mt], &bb[q >> 1][(q & 1) << 1]);
        ldsm_x4(al[0], aLo + ka);
        ldsm_x4(al[1], aLo + 16u * SA + ka);
        #pragma unroll
        for (int mt = 0; mt < 2; mt++)
            #pragma unroll
            for (int q = 0; q < 4; q++)
                mma16816(acc[mt][q], al[mt], &bb[q >> 1][(q & 1) << 1]);
        ldsm_x4(bb[0], bLo + kb);
        ldsm_x4(bb[1], bLo + 16u * SB + kb);
        #pragma unroll
        for (int mt = 0; mt < 2; mt++)
            #pragma unroll
            for (int q = 0; q < 4; q++)
                mma16816(acc[mt][q], ah[mt], &bb[q >> 1][(q & 1) << 1]);
    }
}

// 32x32 warp-tile SINGLE-term fp16 GEMM, KS ksteps, stride 272 both operands.
template<int KS>
__device__ __forceinline__ void gemm_f16(float (&acc)[2][4][4],
    uint32_t aBase, uint32_t bBase, int lane)
{
    const uint32_t aOff = (uint32_t)(lane & 15) * TSTRIDE + (uint32_t)((lane >> 4) << 4);
    const uint32_t bOff = (uint32_t)(((lane >> 4) << 3) + (lane & 7)) * TSTRIDE
                        + (uint32_t)(((lane >> 3) & 1) << 4);
    #pragma unroll
    for (int ks = 0; ks < KS; ks++) {
        const uint32_t ka = aOff + (uint32_t)ks * 32u;
        const uint32_t kb = bOff + (uint32_t)ks * 32u;
        uint32_t ah[2][4], bb[2][4];
        ldsm_x4(ah[0], aBase + ka);
        ldsm_x4(ah[1], aBase + 16u * TSTRIDE + ka);
        ldsm_x4(bb[0], bBase + kb);
        ldsm_x4(bb[1], bBase + 16u * TSTRIDE + kb);
        #pragma unroll
        for (int mt = 0; mt < 2; mt++)
            #pragma unroll
            for (int q = 0; q < 4; q++)
                mma16816h(acc[mt][q], ah[mt], &bb[q >> 1][(q & 1) << 1]);
    }
}

// async copy one half-K (64k) weight tile (hi + lo planes), 256-thread blocks
__device__ __forceinline__ void load_w_half(uint32_t dst, int mat, int half){
    const unsigned char* src = g_wt + (size_t)mat * 69632 + half * 128;
    #pragma unroll
    for (int it = 0; it < 8; it++) {
        int lin = threadIdx.x + it * 256;      // 0..2047
        int plane = lin >> 10, idx = lin & 1023;
        int r = idx >> 3, c = idx & 7;
        cp16(dst + (uint32_t)plane * 18432u + (uint32_t)r * HSTRIDE + (uint32_t)c * 16u,
             src + (size_t)plane * 34816 + (size_t)r * 272 + c * 16);
    }
    cp_commit();
}

// LN one row (128 cols) by a full warp; write split bf16 into A tile (272B stride).
__device__ __forceinline__ void ln_row(char* smp, uint32_t hiOff, uint32_t loOff,
    int row, int lane, const float* x,
    float g0, float g1, float g2, float g3,
    float c0, float c1, float c2, float c3)
{
    float v0 = x[lane], v1 = x[lane+32], v2 = x[lane+64], v3 = x[lane+96];
    float s = v0 + v1 + v2 + v3;
    #pragma unroll
    for (int o = 16; o > 0; o >>= 1) s += __shfl_xor_sync(0xffffffffu, s, o);
    float mean = s * (1.0f / 128.0f);
    float d0 = v0-mean, d1 = v1-mean, d2 = v2-mean, d3 = v3-mean;
    float q = d0*d0 + d1*d1 + d2*d2 + d3*d3;
    #pragma unroll
    for (int o = 16; o > 0; o >>= 1) q += __shfl_xor_sync(0xffffffffu, q, o);
    float inv = rsqrtf(q * (1.0f / 128.0f) + 1e-5f);
    float y0 = d0*inv*g0 + c0, y1 = d1*inv*g1 + c1;
    float y2 = d2*inv*g2 + c2, y3 = d3*inv*g3 + c3;
    uint16_t* aH = (uint16_t*)(smp + hiOff);
    uint16_t* aL = (uint16_t*)(smp + loOff);
    uint16_t h;
    h = bf16bits(y0); aH[row*136 + lane]      = h; aL[row*136 + lane]      = bf16bits(y0 - bf2f(h));
    h = bf16bits(y1); aH[row*136 + lane + 32] = h; aL[row*136 + lane + 32] = bf16bits(y1 - bf2f(h));
    h = bf16bits(y2); aH[row*136 + lane + 64] = h; aL[row*136 + lane + 64] = bf16bits(y2 - bf2f(h));
    h = bf16bits(y3); aH[row*136 + lane + 96] = h; aL[row*136 + lane + 96] = bf16bits(y3 - bf2f(h));
}

// ============================================================
// Kernel W: pre-split the 6 weight matrices (0=wga 1=wpa 2=wgb 3=wpb 4=wog 5=wop)
// ============================================================
__global__ void __launch_bounds__(512, 1) prep_w_kernel(
    const float* __restrict__ wga, const float* __restrict__ wpa,
    const float* __restrict__ wgb, const float* __restrict__ wpb,
    const float* __restrict__ wog, const float* __restrict__ wop)
{
    const float* Ws[6] = {wga, wpa, wgb, wpb, wog, wop};
    const float* W = Ws[blockIdx.x];
    unsigned char* dst = g_wt + (size_t)blockIdx.x * 69632;
    #pragma unroll
    for (int it = 0; it < 8; it++) {
        int lin = threadIdx.x + it * 512;
        int r = lin >> 5, c4 = (lin & 31) << 2;
        float4 v = *(const float4*)(W + r * 128 + c4);
        uint2 hh, ll;
        split4(v, hh, ll);
        *(uint2*)(dst + r * TSTRIDE + c4 * 2) = hh;
        *(uint2*)(dst + 34816 + r * TSTRIDE + c4 * 2) = ll;
    }
}

// ============================================================
// Kernel P: LN(z) + 5 projections.  64 rows, 256 threads (8 warps, 2m x 4n), 2 CTAs/SM.
// smem: A_hi 0, A_lo 17408, WBUF0 34816 (36864), WBUF1 71680 (36864) = 108544.
// a/b epilogue: single fp16 plane staged in WBUF1.
// ============================================================
#define PR_AHI 0u
#define PR_ALO 17408u
#define PR_WB0 34816u
#define PR_WB1 71680u
#define PR_SMEM 108544

__global__ void __launch_bounds__(256, 2) proj_kernel(
    const float* __restrict__ z, const float* __restrict__ gin, const float* __restrict__ bin,
    const float* __restrict__ bga, const float* __restrict__ bpa,
    const float* __restrict__ bgb, const float* __restrict__ bpb,
    const float* __restrict__ bog)
{
    extern __shared__ char smp[];
    const uint32_t sb = smem_u32(smp);
    const int tid = threadIdx.x, wid = tid >> 5, lane = tid & 31;

    const size_t m0 = (size_t)blockIdx.x * 64;
    const int b  = (int)(m0 >> 16);
    const int ii = (int)((m0 >> 8) & 255);
    const int k0 = (int)(m0 & 255);

    // async prefetch: z tile -> WB1 stage [64][128] f32, and wga.h0 -> WB0
    {
        const float* zsrc = z + m0 * 128;
        #pragma unroll
        for (int it = 0; it < 8; it++) {
            int lin = tid + it * 256;
            int r = lin >> 5, c = lin & 31;
            cp16(sb + PR_WB1 + (uint32_t)r * 512u + (uint32_t)c * 16u, zsrc + r * 128 + c * 4);
        }
        cp_commit();
    }
    load_w_half(sb + PR_WB0, 0, 0);
    cp_wait0(); __syncthreads();

    {   // LN rows (from smem stage) -> split A tiles (8 rows per warp)
        const float* zs = (const float*)(smp + PR_WB1);
        const float g0 = gin[lane], g1 = gin[lane+32], g2 = gin[lane+64], g3 = gin[lane+96];
        const float c0 = bin[lane], c1 = bin[lane+32], c2 = bin[lane+64], c3 = bin[lane+96];
        #pragma unroll
        for (int r = 0; r < 8; r++) {
            int row = wid * 8 + r;
            ln_row(smp, PR_AHI, PR_ALO, row, lane, zs + row * 128,
                   g0, g1, g2, g3, c0, c1, c2, c3);
        }
    }
    __syncthreads();        // z stage consumed before WB1 is overwritten

    const int m0w = (wid >> 2) * 32, n0w = (wid & 3) * 32;
    const uint32_t aH0 = sb + PR_AHI + (uint32_t)m0w * TSTRIDE;
    const uint32_t aL0 = sb + PR_ALO + (uint32_t)m0w * TSTRIDE;
    const uint32_t b0n = sb + PR_WB0 + (uint32_t)n0w * HSTRIDE;
    const uint32_t b1n = sb + PR_WB1 + (uint32_t)n0w * HSTRIDE;

    // ---- two gated-pair phases (invariant at entry: WB0 = (gmat, h0), no cp pending) ----
    for (int ph = 0; ph < 2; ph++) {
        const int gmat = ph ? 2 : 0, pmat = ph ? 3 : 1;
        const float* bg = ph ? bgb : bga;
        const float* bp = ph ? bpb : bpa;

        float accG[2][4][4] = {}, accP[2][4][4] = {};

        load_w_half(sb + PR_WB1, gmat, 1);
        gemm32<TSTRIDE, HSTRIDE>(accG, aH0, aL0, b0n, b0n + 18432u, lane);
        cp_wait0(); __syncthreads();

        load_w_half(sb + PR_WB0, pmat, 0);
        gemm32<TSTRIDE, HSTRIDE>(accG, aH0 + 128u, aL0 + 128u, b1n, b1n + 18432u, lane);
        cp_wait0(); __syncthreads();

        load_w_half(sb + PR_WB1, pmat, 1);
        gemm32<TSTRIDE, HSTRIDE>(accP, aH0, aL0, b0n, b0n + 18432u, lane);
        cp_wait0(); __syncthreads();

        gemm32<TSTRIDE, HSTRIDE>(accP, aH0 + 128u, aL0 + 128u, b1n, b1n + 18432u, lane);
        __syncthreads();

        load_w_half(sb + PR_WB0, ph ? 4 : 2, 0);    // next phase h0 — overlaps epilogue

        // stage transposed into WBUF1: single fp16 plane [d 128][m 72]
        uint16_t* stH = (uint16_t*)(smp + PR_WB1);
        #pragma unroll
        for (int mt = 0; mt < 2; mt++)
            #pragma unroll
            for (int q = 0; q < 4; q++) {
                int n = n0w + q * 8 + 2 * (lane & 3);
                float2 bg2 = *(const float2*)(bg + n);
                float2 bp2 = *(const float2*)(bp + n);
                #pragma unroll
                for (int rh = 0; rh < 2; rh++) {
                    int m = m0w + mt * 16 + (lane >> 2) + rh * 8;
                    float v0 = sigmoidf_(accG[mt][q][rh*2]   + bg2.x) * (accP[mt][q][rh*2]   + bp2.x);
                    float v1 = sigmoidf_(accG[mt][q][rh*2+1] + bg2.y) * (accP[mt][q][rh*2+1] + bp2.y);
                    __half h0 = __float2half(v0), h1 = __float2half(v1);
                    stH[n * 72 + m]       = *reinterpret_cast<uint16_t*>(&h0);
                    stH[(n + 1) * 72 + m] = *reinterpret_cast<uint16_t*>(&h1);
                }
            }
        __syncthreads();

        __half* dst = ph ? g_bt : g_at;
        #pragma unroll
        for (int it = 0; it < 4; it++) {
            int lin = tid + it * 256;               // 0..1023
            int d = lin >> 3, m8 = (lin & 7) << 3;
            uint4 v = *(const uint4*)(smp + PR_WB1 + d * HSTRIDE + m8 * 2);
            *(uint4*)(dst + ((size_t)(b * 128 + d)) * 65536 + (size_t)ii * 256 + k0 + m8) = v;
        }
        __syncthreads();                            // stage consumed
        load_w_half(sb + PR_WB1, ph ? 4 : 3, ph ? 1 : 0);  // next P.h0 (or wog.h1)
        cp_wait0(); __syncthreads();
    }

    // ---- gate phase (WB0 = wog.h0, WB1 = wog.h1; both resident) ----
    float acc[2][4][4] = {};
    gemm32<TSTRIDE, HSTRIDE>(acc, aH0, aL0, b0n, b0n + 18432u, lane);
    gemm32<TSTRIDE, HSTRIDE>(acc, aH0 + 128u, aL0 + 128u, b1n, b1n + 18432u, lane);

    #pragma unroll
    for (int mt = 0; mt < 2; mt++)
        #pragma unroll
        for (int q = 0; q < 4; q++) {
            int n = n0w + q * 8 + 2 * (lane & 3);
            float2 bo2 = *(const float2*)(bog + n);
            #pragma unroll
            for (int rh = 0; rh < 2; rh++) {
                int m = m0w + mt * 16 + (lane >> 2) + rh * 8;
                __half2 o = __floats2half2_rn(sigmoidf_(acc[mt][q][rh*2]   + bo2.x),
                                              sigmoidf_(acc[mt][q][rh*2+1] + bo2.y));
                *(__half2*)(g_gate + (m0 + m) * 128 + n) = o;
            }
        }
}

// ============================================================
// Kernel T: triangle einsum, SINGLE-term fp16. C tile 64x128, 256 threads, 2 CTAs/SM.
// K = 256 in 2 chunks of 128, double-buffered (2 x 52224 = 104448 B).
// Chunk layout: A (64 rows, 272B stride) @0 (17408), B (128 rows) @17408 (34816).
// grid.x = 4096: bd = bx>>3, i0 = ((bx>>1)&3)*64, j0 = (bx&1)*128
// ============================================================
#define TR_CHSZ 52224u
#define TR_SMEM 104448

__device__ __forceinline__ void tri_load_chunk(uint32_t bufBase, size_t base,
                                               int i0, int j0, int kb)
{
    #pragma unroll
    for (int it = 0; it < 12; it++) {
        int lin = threadIdx.x + it * 256;          // 0..3071
        if (lin < 1024) {                          // A: 64 rows x 128 k fp16
            int r = lin >> 4, c = lin & 15;
            cp16(bufBase + (uint32_t)r * TSTRIDE + (uint32_t)c * 16u,
                 g_at + base + (size_t)(i0 + r) * 256 + kb * 128 + c * 8);
        } else {                                   // B: 128 rows x 128 k fp16
            int l2 = lin - 1024;
            int r = l2 >> 4, c = l2 & 15;
            cp16(bufBase + 17408u + (uint32_t)r * TSTRIDE + (uint32_t)c * 16u,
                 g_bt + base + (size_t)(j0 + r) * 256 + kb * 128 + c * 8);
        }
    }
    cp_commit();
}

__global__ void __launch_bounds__(256, 2) tri_kernel()
{
    extern __shared__ char smp[];
    const uint32_t sb = smem_u32(smp);
    const int tid = threadIdx.x, wid = tid >> 5, lane = tid & 31;
    const int bx = blockIdx.x;
    const int bd = bx >> 3;
    const int i0 = ((bx >> 1) & 3) * 64;
    const int j0 = (bx & 1) * 128;
    const size_t base = (size_t)bd * 65536;

    const int m0w = (wid >> 2) * 32, n0w = (wid & 3) * 32;
    float acc[2][4][4] = {};

    tri_load_chunk(sb, base, i0, j0, 0);
    #pragma unroll
    for (int kb = 0; kb < 2; kb++) {
        cp_wait0(); __syncthreads();
        if (kb < 1) tri_load_chunk(sb + TR_CHSZ, base, i0, j0, 1);
        const uint32_t bf = sb + kb * TR_CHSZ;
        gemm_f16<8>(acc, bf + (uint32_t)m0w * TSTRIDE,
                         bf + 17408u + (uint32_t)n0w * TSTRIDE, lane);
    }

    #pragma unroll
    for (int mt = 0; mt < 2; mt++)
        #pragma unroll
        for (int q = 0; q < 4; q++) {
            int n = n0w + q * 8 + 2 * (lane & 3);
            #pragma unroll
            for (int rh = 0; rh < 2; rh++) {
                int m = m0w + mt * 16 + (lane >> 2) + rh * 8;
                __half2 o = __floats2half2_rn(acc[mt][q][rh*2], acc[mt][q][rh*2+1]);
                *(__half2*)(g_ot + base + (size_t)(i0 + m) * 256 + j0 + n) = o;
            }
        }
}

// ============================================================
// Kernel F: async gather + column-LN + wop + gate.  64 p-rows, 256 threads, 3 CTAs/SM.
// smem: A_hi 0, A_lo 17408; S fp16 [128 d][72] @34816 (dead after LN);
//       W halves overlay S @34816 (36864).  Total 71680.
// grid.x = 4096: b = bx>>10, p0 = (bx&1023)*64
// ============================================================
#define FN_AHI 0u
#define FN_ALO 17408u
#define FN_S   34816u
#define FN_W   34816u
#define FN_SMEM 71680

__global__ void __launch_bounds__(256, 3) final_kernel(
    const float* __restrict__ gout, const float* __restrict__ bout,
    const float* __restrict__ bop, float* __restrict__ outp)
{
    extern __shared__ char smp[];
    const uint32_t sb = smem_u32(smp);
    const int tid = threadIdx.x, wid = tid >> 5, lane = tid & 31;
    const int b  = blockIdx.x >> 10;
    const int p0 = (blockIdx.x & 1023) * 64;

    // async raw gather: S[d][p] <- g_ot[b][d][p0 .. p0+63] fp16 (d-major, coalesced)
    {
        const __half* src = g_ot + (size_t)b * 128 * 65536 + p0;
        #pragma unroll
        for (int it = 0; it < 4; it++) {
            int lin = tid + it * 256;              // 0..1023 16B chunks
            int d = lin >> 3, c = lin & 7;
            cp16(sb + FN_S + (uint32_t)d * 144u + (uint32_t)c * 16u,
                 src + (size_t)d * 65536 + c * 8);
        }
        cp_commit();
    }
    cp_wait0(); __syncthreads();

    // column LN: warp w owns p = 8w..8w+7; 4 lanes per column (part = lane&3),
    // each lane covers d = part*32 + ((i + 2*part)&31).
    {
        const __half* S = (const __half*)(smp + FN_S);
        const int c  = lane >> 2, part = lane & 3;
        const int p  = wid * 8 + c;
        float s1 = 0.f;
        #pragma unroll
        for (int i = 0; i < 32; i++) {
            int d = part * 32 + ((i + 2 * part) & 31);
            s1 += __half2float(S[d * 72 + p]);
        }
        s1 += __shfl_xor_sync(0xffffffffu, s1, 1);
        s1 += __shfl_xor_sync(0xffffffffu, s1, 2);
        const float mean = s1 * (1.0f / 128.0f);
        float s2 = 0.f;
        #pragma unroll
        for (int i = 0; i < 32; i++) {
            int d = part * 32 + ((i + 2 * part) & 31);
            float v = __half2float(S[d * 72 + p]) - mean;
            s2 += v * v;
        }
        s2 += __shfl_xor_sync(0xffffffffu, s2, 1);
        s2 += __shfl_xor_sync(0xffffffffu, s2, 2);
        const float inv = rsqrtf(s2 * (1.0f / 128.0f) + 1e-5f);
        uint16_t* aH = (uint16_t*)(smp + FN_AHI);
        uint16_t* aL = (uint16_t*)(smp + FN_ALO);
        #pragma unroll
        for (int i = 0; i < 32; i++) {
            int d = part * 32 + ((i + 2 * part) & 31);
            float y = (__half2float(S[d * 72 + p]) - mean) * inv * gout[d] + bout[d];
            uint16_t h = bf16bits(y);
            aH[p * 136 + d] = h;
            aL[p * 136 + d] = bf16bits(y - bf2f(h));
        }
    }
    __syncthreads();            // S fully consumed before W overlays it

    const int m0w = (wid >> 2) * 32, n0w = (wid & 3) * 32;
    const uint32_t aH0 = sb + FN_AHI + (uint32_t)m0w * TSTRIDE;
    const uint32_t aL0 = sb + FN_ALO + (uint32_t)m0w * TSTRIDE;
    const uint32_t wn  = sb + FN_W + (uint32_t)n0w * HSTRIDE;

    float acc[2][4][4] = {};
    load_w_half(sb + FN_W, 5, 0);
    cp_wait0(); __syncthreads();
    gemm32<TSTRIDE, HSTRIDE>(acc, aH0, aL0, wn, wn + 18432u, lane);
    __syncthreads();
    load_w_half(sb + FN_W, 5, 1);
    cp_wait0(); __syncthreads();
    gemm32<TSTRIDE, HSTRIDE>(acc, aH0 + 128u, aL0 + 128u, wn, wn + 18432u, lane);

    #pragma unroll
    for (int mt = 0; mt < 2; mt++)
        #pragma unroll
        for (int q = 0; q < 4; q++) {
            int n = n0w + q * 8 + 2 * (lane & 3);
            float2 bo2 = *(const float2*)(bop + n);
            #pragma unroll
            for (int rh = 0; rh < 2; rh++) {
                int m = m0w + mt * 16 + (lane >> 2) + rh * 8;
                size_t gi = ((size_t)b * 65536 + p0 + m) * 128 + n;
                float2 g = __half22float2(*(const __half2*)(g_gate + gi));
                float2 o;
                o.x = g.x * (acc[mt][q][rh*2]   + bo2.x);
                o.y = g.y * (acc[mt][q][rh*2+1] + bo2.y);
                *(float2*)(outp + gi) = o;
            }
        }
}

// ============================================================
// launch
// ============================================================
extern "C" void kernel_launch(void* const* d_in, const int* in_sizes, int n_in,
                              void* d_out, int out_size)
{
    const float* z    = (const float*)d_in[0];
    const float* gin  = (const float*)d_in[1];
    const float* bin  = (const float*)d_in[2];
    const float* wpa  = (const float*)d_in[3];
    const float* bpa  = (const float*)d_in[4];
    const float* wga  = (const float*)d_in[5];
    const float* bga  = (const float*)d_in[6];
    const float* wpb  = (const float*)d_in[7];
    const float* bpb  = (const float*)d_in[8];
    const float* wgb  = (const float*)d_in[9];
    const float* bgb  = (const float*)d_in[10];
    const float* gout = (const float*)d_in[11];
    const float* bout = (const float*)d_in[12];
    const float* wop  = (const float*)d_in[13];
    const float* bop  = (const float*)d_in[14];
    const float* wog  = (const float*)d_in[15];
    const float* bog  = (const float*)d_in[16];
    float* outp = (float*)d_out;

    cudaFuncSetAttribute(proj_kernel,  cudaFuncAttributeMaxDynamicSharedMemorySize, PR_SMEM);
    cudaFuncSetAttribute(tri_kernel,   cudaFuncAttributeMaxDynamicSharedMemorySize, TR_SMEM);
    cudaFuncSetAttribute(final_kernel, cudaFuncAttributeMaxDynamicSharedMemorySize, FN_SMEM);

    prep_w_kernel<<<6, 512>>>(wga, wpa, wgb, wpb, wog, wop);
    proj_kernel<<<4096, 256, PR_SMEM>>>(z, gin, bin, bga, bpa, bgb, bpb, bog);
    tri_kernel<<<4096, 256, TR_SMEM>>>();
    final_kernel<<<4096, 256, FN_SMEM>>>(gout, bout, bop, outp);
}

// round 16
// speedup vs baseline: 1.7202x; 1.4832x over previous
#include <cuda_runtime.h>
#include <cuda_bf16.h>
#include <cuda_fp16.h>
#include <stdint.h>

#define ELEMS ((size_t)4*256*256*128)   // 33.5M

// ---------------- scratch ----------------
__device__ __align__(16) __half g_at[ELEMS];     // fp16 gated projection a (b,d,i,k)
__device__ __align__(16) __half g_bt[ELEMS];     // fp16 gated projection b (b,d,j,k)
__device__ __align__(16) __half g_gate[ELEMS];   // fp16 sigmoid gate
__device__ __align__(16) __half g_ot[ELEMS];     // fp16 triangle result (b,d,i,j)
// fp16 weight tile images: 6 mats x 34816 B (128 rows x 256 B data, 272 B stride)
__device__ __align__(16) unsigned char g_wt[6 * 34816];

// ---------------- helpers ----------------
__device__ __forceinline__ uint32_t smem_u32(const void* p){
    uint32_t a;
    asm("{ .reg .u64 t; cvta.to.shared.u64 t, %1; cvt.u32.u64 %0, t; }" : "=r"(a) : "l"(p));
    return a;
}
__device__ __forceinline__ void ldsm_x4(uint32_t* r, uint32_t a){
    asm volatile("ldmatrix.sync.aligned.m8n8.x4.shared.b16 {%0,%1,%2,%3}, [%4];"
        : "=r"(r[0]), "=r"(r[1]), "=r"(r[2]), "=r"(r[3]) : "r"(a));
}
__device__ __forceinline__ void mma16816h(float* c, const uint32_t* a, const uint32_t* b){
    asm volatile("mma.sync.aligned.m16n8k16.row.col.f32.f16.f16.f32 "
        "{%0,%1,%2,%3}, {%4,%5,%6,%7}, {%8,%9}, {%0,%1,%2,%3};"
        : "+f"(c[0]), "+f"(c[1]), "+f"(c[2]), "+f"(c[3])
        : "r"(a[0]), "r"(a[1]), "r"(a[2]), "r"(a[3]), "r"(b[0]), "r"(b[1]));
}
__device__ __forceinline__ void cp16(uint32_t dst, const void* src){
    asm volatile("cp.async.cg.shared.global [%0], [%1], 16;" :: "r"(dst), "l"(src));
}
__device__ __forceinline__ void cp_commit(){
    asm volatile("cp.async.commit_group;" ::: "memory");
}
__device__ __forceinline__ void cp_wait0(){
    asm volatile("cp.async.wait_group 0;" ::: "memory");
}
__device__ __forceinline__ float sigmoidf_(float x){ return 1.0f / (1.0f + __expf(-x)); }
__device__ __forceinline__ uint16_t h16bits(float v){
    __half h = __float2half(v);
    return *reinterpret_cast<uint16_t*>(&h);
}

#define TSTRIDE 272u   // full-K (128) 16-bit tile row stride in bytes

// 32x32 warp-tile SINGLE-term fp16 GEMM, KS ksteps, stride 272 both operands.
template<int KS>
__device__ __forceinline__ void gemm_f16(float (&acc)[2][4][4],
    uint32_t aBase, uint32_t bBase, int lane)
{
    const uint32_t aOff = (uint32_t)(lane & 15) * TSTRIDE + (uint32_t)((lane >> 4) << 4);
    const uint32_t bOff = (uint32_t)(((lane >> 4) << 3) + (lane & 7)) * TSTRIDE
                        + (uint32_t)(((lane >> 3) & 1) << 4);
    #pragma unroll
    for (int ks = 0; ks < KS; ks++) {
        const uint32_t ka = aOff + (uint32_t)ks * 32u;
        const uint32_t kb = bOff + (uint32_t)ks * 32u;
        uint32_t ah[2][4], bb[2][4];
        ldsm_x4(ah[0], aBase + ka);
        ldsm_x4(ah[1], aBase + 16u * TSTRIDE + ka);
        ldsm_x4(bb[0], bBase + kb);
        ldsm_x4(bb[1], bBase + 16u * TSTRIDE + kb);
        #pragma unroll
        for (int mt = 0; mt < 2; mt++)
            #pragma unroll
            for (int q = 0; q < 4; q++)
                mma16816h(acc[mt][q], ah[mt], &bb[q >> 1][(q & 1) << 1]);
    }
}

// async copy one full fp16 weight tile (128 rows x 256 B, 272 stride), 256 threads
__device__ __forceinline__ void load_w_full(uint32_t dst, int mat){
    const unsigned char* src = g_wt + (size_t)mat * 34816;
    #pragma unroll
    for (int it = 0; it < 8; it++) {
        int lin = threadIdx.x + it * 256;      // 0..2047
        int r = lin >> 4, c = lin & 15;
        cp16(dst + (uint32_t)r * TSTRIDE + (uint32_t)c * 16u,
             src + (size_t)r * 272 + c * 16);
    }
    cp_commit();
}

// LN one row (128 cols) by a full warp; write fp16 into A tile (272B stride).
__device__ __forceinline__ void ln_row_f16(char* smp, uint32_t aOff,
    int row, int lane, const float* x,
    float g0, float g1, float g2, float g3,
    float c0, float c1, float c2, float c3)
{
    float v0 = x[lane], v1 = x[lane+32], v2 = x[lane+64], v3 = x[lane+96];
    float s = v0 + v1 + v2 + v3;
    #pragma unroll
    for (int o = 16; o > 0; o >>= 1) s += __shfl_xor_sync(0xffffffffu, s, o);
    float mean = s * (1.0f / 128.0f);
    float d0 = v0-mean, d1 = v1-mean, d2 = v2-mean, d3 = v3-mean;
    float q = d0*d0 + d1*d1 + d2*d2 + d3*d3;
    #pragma unroll
    for (int o = 16; o > 0; o >>= 1) q += __shfl_xor_sync(0xffffffffu, q, o);
    float inv = rsqrtf(q * (1.0f / 128.0f) + 1e-5f);
    uint16_t* aH = (uint16_t*)(smp + aOff);
    aH[row*136 + lane]      = h16bits(d0*inv*g0 + c0);
    aH[row*136 + lane + 32] = h16bits(d1*inv*g1 + c1);
    aH[row*136 + lane + 64] = h16bits(d2*inv*g2 + c2);
    aH[row*136 + lane + 96] = h16bits(d3*inv*g3 + c3);
}

// ============================================================
// Kernel W: pre-convert the 6 weight matrices to fp16 tile images
// (0=wga 1=wpa 2=wgb 3=wpb 4=wog 5=wop)
// ============================================================
__global__ void __launch_bounds__(512, 1) prep_w_kernel(
    const float* __restrict__ wga, const float* __restrict__ wpa,
    const float* __restrict__ wgb, const float* __restrict__ wpb,
    const float* __restrict__ wog, const float* __restrict__ wop)
{
    const float* Ws[6] = {wga, wpa, wgb, wpb, wog, wop};
    const float* W = Ws[blockIdx.x];
    unsigned char* dst = g_wt + (size_t)blockIdx.x * 34816;
    #pragma unroll
    for (int it = 0; it < 8; it++) {
        int lin = threadIdx.x + it * 512;
        int r = lin >> 5, c4 = (lin & 31) << 2;
        float4 v = *(const float4*)(W + r * 128 + c4);
        uint2 hh;
        hh.x = (uint32_t)h16bits(v.x) | ((uint32_t)h16bits(v.y) << 16);
        hh.y = (uint32_t)h16bits(v.z) | ((uint32_t)h16bits(v.w) << 16);
        *(uint2*)(dst + r * TSTRIDE + c4 * 2) = hh;
    }
}

// ============================================================
// Kernel P: LN(z) + 5 projections, fp16 single-term.  64 rows, 256 threads, 2 CTAs/SM.
// smem: A 0 (17408), WB0 17408 (34816), WB1 52224 (34816) = 87040.
// z stage (32768) overlays WB0; pair epilogue stage (18432) overlays WB0.
// ============================================================
#define PR_A   0u
#define PR_WB0 17408u
#define PR_WB1 52224u
#define PR_SMEM 87040

__global__ void __launch_bounds__(256, 2) proj_kernel(
    const float* __restrict__ z, const float* __restrict__ gin, const float* __restrict__ bin,
    const float* __restrict__ bga, const float* __restrict__ bpa,
    const float* __restrict__ bgb, const float* __restrict__ bpb,
    const float* __restrict__ bog)
{
    extern __shared__ char smp[];
    const uint32_t sb = smem_u32(smp);
    const int tid = threadIdx.x, wid = tid >> 5, lane = tid & 31;

    const size_t m0 = (size_t)blockIdx.x * 64;
    const int b  = (int)(m0 >> 16);
    const int ii = (int)((m0 >> 8) & 255);
    const int k0 = (int)(m0 & 255);

    // async prefetch: z tile -> WB0 stage [64][128] f32, wga -> WB1
    {
        const float* zsrc = z + m0 * 128;
        #pragma unroll
        for (int it = 0; it < 8; it++) {
            int lin = tid + it * 256;
            int r = lin >> 5, c = lin & 31;
            cp16(sb + PR_WB0 + (uint32_t)r * 512u + (uint32_t)c * 16u, zsrc + r * 128 + c * 4);
        }
        cp_commit();
    }
    load_w_full(sb + PR_WB1, 0);
    cp_wait0(); __syncthreads();

    {   // LN rows (from smem stage) -> fp16 A tile (8 rows per warp)
        const float* zs = (const float*)(smp + PR_WB0);
        const float g0 = gin[lane], g1 = gin[lane+32], g2 = gin[lane+64], g3 = gin[lane+96];
        const float c0 = bin[lane], c1 = bin[lane+32], c2 = bin[lane+64], c3 = bin[lane+96];
        #pragma unroll
        for (int r = 0; r < 8; r++) {
            int row = wid * 8 + r;
            ln_row_f16(smp, PR_A, row, lane, zs + row * 128,
                       g0, g1, g2, g3, c0, c1, c2, c3);
        }
    }
    __syncthreads();        // z stage consumed
    load_w_full(sb + PR_WB0, 1);     // wpa
    cp_wait0(); __syncthreads();

    const int m0w = (wid >> 2) * 32, n0w = (wid & 3) * 32;
    const uint32_t aW  = sb + PR_A + (uint32_t)m0w * TSTRIDE;
    const uint32_t w0n = sb + PR_WB0 + (uint32_t)n0w * TSTRIDE;
    const uint32_t w1n = sb + PR_WB1 + (uint32_t)n0w * TSTRIDE;

    // ---- two gated-pair phases (entry: WB1 = G mat, WB0 = P mat, no cp pending) ----
    for (int ph = 0; ph < 2; ph++) {
        const float* bg = ph ? bgb : bga;
        const float* bp = ph ? bpb : bpa;

        float accG[2][4][4] = {}, accP[2][4][4] = {};
        gemm_f16<8>(accG, aW, w1n, lane);
        gemm_f16<8>(accP, aW, w0n, lane);
        __syncthreads();                     // both W buffers dead

        load_w_full(sb + PR_WB1, ph ? 4 : 2);   // next G (wgb) or wog — overlaps epilogue

        // stage transposed into WB0: fp16 [d 128][m 72]
        uint16_t* stH = (uint16_t*)(smp + PR_WB0);
        #pragma unroll
        for (int mt = 0; mt < 2; mt++)
            #pragma unroll
            for (int q = 0; q < 4; q++) {
                int n = n0w + q * 8 + 2 * (lane & 3);
                float2 bg2 = *(const float2*)(bg + n);
                float2 bp2 = *(const float2*)(bp + n);
                #pragma unroll
                for (int rh = 0; rh < 2; rh++) {
                    int m = m0w + mt * 16 + (lane >> 2) + rh * 8;
                    float v0 = sigmoidf_(accG[mt][q][rh*2]   + bg2.x) * (accP[mt][q][rh*2]   + bp2.x);
                    float v1 = sigmoidf_(accG[mt][q][rh*2+1] + bg2.y) * (accP[mt][q][rh*2+1] + bp2.y);
                    stH[n * 72 + m]       = h16bits(v0);
                    stH[(n + 1) * 72 + m] = h16bits(v1);
                }
            }
        __syncthreads();

        __half* dst = ph ? g_bt : g_at;
        #pragma unroll
        for (int it = 0; it < 4; it++) {
            int lin = tid + it * 256;               // 0..1023
            int d = lin >> 3, m8 = (lin & 7) << 3;
            uint4 v = *(const uint4*)(smp + PR_WB0 + d * 144u + m8 * 2);
            *(uint4*)(dst + ((size_t)(b * 128 + d)) * 65536 + (size_t)ii * 256 + k0 + m8) = v;
        }
        __syncthreads();                            // stage consumed
        if (ph == 0) load_w_full(sb + PR_WB0, 3);   // wpb
        cp_wait0(); __syncthreads();
    }

    // ---- gate phase (WB1 = wog) ----
    float acc[2][4][4] = {};
    gemm_f16<8>(acc, aW, w1n, lane);

    #pragma unroll
    for (int mt = 0; mt < 2; mt++)
        #pragma unroll
        for (int q = 0; q < 4; q++) {
            int n = n0w + q * 8 + 2 * (lane & 3);
            float2 bo2 = *(const float2*)(bog + n);
            #pragma unroll
            for (int rh = 0; rh < 2; rh++) {
                int m = m0w + mt * 16 + (lane >> 2) + rh * 8;
                __half2 o = __floats2half2_rn(sigmoidf_(acc[mt][q][rh*2]   + bo2.x),
                                              sigmoidf_(acc[mt][q][rh*2+1] + bo2.y));
                *(__half2*)(g_gate + (m0 + m) * 128 + n) = o;
            }
        }
}

// ============================================================
// Kernel T: triangle einsum, single-term fp16. C tile 64x128, 256 threads, 2 CTAs/SM.
// K = 256 in 2 chunks of 128, double-buffered (2 x 52224 = 104448 B).
// Chunk: A (64 rows) @0 (17408), B (128 rows) @17408 (34816).
// grid.x = 4096: bd = bx>>3, i0 = ((bx>>1)&3)*64, j0 = (bx&1)*128
// ============================================================
#define TR_CHSZ 52224u
#define TR_SMEM 104448

__device__ __forceinline__ void tri_load_chunk(uint32_t bufBase, size_t base,
                                               int i0, int j0, int kb)
{
    #pragma unroll
    for (int it = 0; it < 12; it++) {
        int lin = threadIdx.x + it * 256;          // 0..3071
        if (lin < 1024) {                          // A: 64 rows x 128 k fp16
            int r = lin >> 4, c = lin & 15;
            cp16(bufBase + (uint32_t)r * TSTRIDE + (uint32_t)c * 16u,
                 g_at + base + (size_t)(i0 + r) * 256 + kb * 128 + c * 8);
        } else {                                   // B: 128 rows x 128 k fp16
            int l2 = lin - 1024;
            int r = l2 >> 4, c = l2 & 15;
            cp16(bufBase + 17408u + (uint32_t)r * TSTRIDE + (uint32_t)c * 16u,
                 g_bt + base + (size_t)(j0 + r) * 256 + kb * 128 + c * 8);
        }
    }
    cp_commit();
}

__global__ void __launch_bounds__(256, 2) tri_kernel()
{
    extern __shared__ char smp[];
    const uint32_t sb = smem_u32(smp);
    const int tid = threadIdx.x, wid = tid >> 5, lane = tid & 31;
    const int bx = blockIdx.x;
    const int bd = bx >> 3;
    const int i0 = ((bx >> 1) & 3) * 64;
    const int j0 = (bx & 1) * 128;
    const size_t base = (size_t)bd * 65536;

    const int m0w = (wid >> 2) * 32, n0w = (wid & 3) * 32;
    float acc[2][4][4] = {};

    tri_load_chunk(sb, base, i0, j0, 0);
    #pragma unroll
    for (int kb = 0; kb < 2; kb++) {
        cp_wait0(); __syncthreads();
        if (kb < 1) tri_load_chunk(sb + TR_CHSZ, base, i0, j0, 1);
        const uint32_t bf = sb + kb * TR_CHSZ;
        gemm_f16<8>(acc, bf + (uint32_t)m0w * TSTRIDE,
                         bf + 17408u + (uint32_t)n0w * TSTRIDE, lane);
    }

    #pragma unroll
    for (int mt = 0; mt < 2; mt++)
        #pragma unroll
        for (int q = 0; q < 4; q++) {
            int n = n0w + q * 8 + 2 * (lane & 3);
            #pragma unroll
            for (int rh = 0; rh < 2; rh++) {
                int m = m0w + mt * 16 + (lane >> 2) + rh * 8;
                __half2 o = __floats2half2_rn(acc[mt][q][rh*2], acc[mt][q][rh*2+1]);
                *(__half2*)(g_ot + base + (size_t)(i0 + m) * 256 + j0 + n) = o;
            }
        }
}

// ============================================================
// Kernel F: async gather + column-LN + wop + gate, fp16.  64 p-rows, 256 threads, 4 CTAs/SM.
// smem: A 0 (17408); S fp16 [128 d][72] @17408 (18432, dead after LN);
//       W overlays S @17408 (34816).  Total 52224.
// grid.x = 4096: b = bx>>10, p0 = (bx&1023)*64
// ============================================================
#define FN_A   0u
#define FN_S   17408u
#define FN_W   17408u
#define FN_SMEM 52224

__global__ void __launch_bounds__(256, 4) final_kernel(
    const float* __restrict__ gout, const float* __restrict__ bout,
    const float* __restrict__ bop, float* __restrict__ outp)
{
    extern __shared__ char smp[];
    const uint32_t sb = smem_u32(smp);
    const int tid = threadIdx.x, wid = tid >> 5, lane = tid & 31;
    const int b  = blockIdx.x >> 10;
    const int p0 = (blockIdx.x & 1023) * 64;

    // async raw gather: S[d][p] <- g_ot[b][d][p0 .. p0+63] fp16 (d-major, coalesced)
    {
        const __half* src = g_ot + (size_t)b * 128 * 65536 + p0;
        #pragma unroll
        for (int it = 0; it < 4; it++) {
            int lin = tid + it * 256;              // 0..1023 16B chunks
            int d = lin >> 3, c = lin & 7;
            cp16(sb + FN_S + (uint32_t)d * 144u + (uint32_t)c * 16u,
                 src + (size_t)d * 65536 + c * 8);
        }
        cp_commit();
    }
    cp_wait0(); __syncthreads();

    // column LN: warp w owns p = 8w..8w+7; 4 lanes per column (part = lane&3),
    // each lane covers d = part*32 + ((i + 2*part)&31).
    {
        const __half* S = (const __half*)(smp + FN_S);
        const int c  = lane >> 2, part = lane & 3;
        const int p  = wid * 8 + c;
        float s1 = 0.f;
        #pragma unroll
        for (int i = 0; i < 32; i++) {
            int d = part * 32 + ((i + 2 * part) & 31);
            s1 += __half2float(S[d * 72 + p]);
        }
        s1 += __shfl_xor_sync(0xffffffffu, s1, 1);
        s1 += __shfl_xor_sync(0xffffffffu, s1, 2);
        const float mean = s1 * (1.0f / 128.0f);
        float s2 = 0.f;
        #pragma unroll
        for (int i = 0; i < 32; i++) {
            int d = part * 32 + ((i + 2 * part) & 31);
            float v = __half2float(S[d * 72 + p]) - mean;
            s2 += v * v;
        }
        s2 += __shfl_xor_sync(0xffffffffu, s2, 1);
        s2 += __shfl_xor_sync(0xffffffffu, s2, 2);
        const float inv = rsqrtf(s2 * (1.0f / 128.0f) + 1e-5f);
        uint16_t* aH = (uint16_t*)(smp + FN_A);
        #pragma unroll
        for (int i = 0; i < 32; i++) {
            int d = part * 32 + ((i + 2 * part) & 31);
            float y = (__half2float(S[d * 72 + p]) - mean) * inv * gout[d] + bout[d];
            aH[p * 136 + d] = h16bits(y);
        }
    }
    __syncthreads();            // S consumed before W overlays it
    load_w_full(sb + FN_W, 5);
    cp_wait0(); __syncthreads();

    const int m0w = (wid >> 2) * 32, n0w = (wid & 3) * 32;
    float acc[2][4][4] = {};
    gemm_f16<8>(acc, sb + FN_A + (uint32_t)m0w * TSTRIDE,
                     sb + FN_W + (uint32_t)n0w * TSTRIDE, lane);

    #pragma unroll
    for (int mt = 0; mt < 2; mt++)
        #pragma unroll
        for (int q = 0; q < 4; q++) {
            int n = n0w + q * 8 + 2 * (lane & 3);
            float2 bo2 = *(const float2*)(bop + n);
            #pragma unroll
            for (int rh = 0; rh < 2; rh++) {
                int m = m0w + mt * 16 + (lane >> 2) + rh * 8;
                size_t gi = ((size_t)b * 65536 + p0 + m) * 128 + n;
                float2 g = __half22float2(*(const __half2*)(g_gate + gi));
                float2 o;
                o.x = g.x * (acc[mt][q][rh*2]   + bo2.x);
                o.y = g.y * (acc[mt][q][rh*2+1] + bo2.y);
                *(float2*)(outp + gi) = o;
            }
        }
}

// ============================================================
// launch
// ============================================================
extern "C" void kernel_launch(void* const* d_in, const int* in_sizes, int n_in,
                              void* d_out, int out_size)
{
    const float* z    = (const float*)d_in[0];
    const float* gin  = (const float*)d_in[1];
    const float* bin  = (const float*)d_in[2];
    const float* wpa  = (const float*)d_in[3];
    const float* bpa  = (const float*)d_in[4];
    const float* wga  = (const float*)d_in[5];
    const float* bga  = (const float*)d_in[6];
    const float* wpb  = (const float*)d_in[7];
    const float* bpb  = (const float*)d_in[8];
    const float* wgb  = (const float*)d_in[9];
    const float* bgb  = (const float*)d_in[10];
    const float* gout = (const float*)d_in[11];
    const float* bout = (const float*)d_in[12];
    const float* wop  = (const float*)d_in[13];
    const float* bop  = (const float*)d_in[14];
    const float* wog  = (const float*)d_in[15];
    const float* bog  = (const float*)d_in[16];
    float* outp = (float*)d_out;

    cudaFuncSetAttribute(proj_kernel,  cudaFuncAttributeMaxDynamicSharedMemorySize, PR_SMEM);
    cudaFuncSetAttribute(tri_kernel,   cudaFuncAttributeMaxDynamicSharedMemorySize, TR_SMEM);
    cudaFuncSetAttribute(final_kernel, cudaFuncAttributeMaxDynamicSharedMemorySize, FN_SMEM);

    prep_w_kernel<<<6, 512>>>(wga, wpa, wgb, wpb, wog, wop);
    proj_kernel<<<4096, 256, PR_SMEM>>>(z, gin, bin, bga, bpa, bgb, bpb, bog);
    tri_kernel<<<4096, 256, TR_SMEM>>>();
    final_kernel<<<4096, 256, FN_SMEM>>>(gout, bout, bop, outp);
}

// round 17
// speedup vs baseline: 1.7323x; 1.0070x over previous
#include <cuda_runtime.h>
#include <cuda_bf16.h>
#include <cuda_fp16.h>
#include <stdint.h>

#define ELEMS ((size_t)4*256*256*128)   // 33.5M

// ---------------- scratch ----------------
__device__ __align__(16) __half g_at[ELEMS];     // fp16 gated projection a (b,d,i,k)
__device__ __align__(16) __half g_bt[ELEMS];     // fp16 gated projection b (b,d,j,k)
__device__ __align__(16) __half g_gate[ELEMS];   // fp16 sigmoid gate
__device__ __align__(16) __half g_ot[ELEMS];     // fp16 triangle result (b,d,i,j)
// fp16 weight tile images: 6 mats x 34816 B (128 rows x 256 B data, 272 B stride)
__device__ __align__(16) unsigned char g_wt[6 * 34816];

// ---------------- helpers ----------------
__device__ __forceinline__ uint32_t smem_u32(const void* p){
    uint32_t a;
    asm("{ .reg .u64 t; cvta.to.shared.u64 t, %1; cvt.u32.u64 %0, t; }" : "=r"(a) : "l"(p));
    return a;
}
__device__ __forceinline__ void ldsm_x4(uint32_t* r, uint32_t a){
    asm volatile("ldmatrix.sync.aligned.m8n8.x4.shared.b16 {%0,%1,%2,%3}, [%4];"
        : "=r"(r[0]), "=r"(r[1]), "=r"(r[2]), "=r"(r[3]) : "r"(a));
}
__device__ __forceinline__ void mma16816h(float* c, const uint32_t* a, const uint32_t* b){
    asm volatile("mma.sync.aligned.m16n8k16.row.col.f32.f16.f16.f32 "
        "{%0,%1,%2,%3}, {%4,%5,%6,%7}, {%8,%9}, {%0,%1,%2,%3};"
        : "+f"(c[0]), "+f"(c[1]), "+f"(c[2]), "+f"(c[3])
        : "r"(a[0]), "r"(a[1]), "r"(a[2]), "r"(a[3]), "r"(b[0]), "r"(b[1]));
}
__device__ __forceinline__ void cp16(uint32_t dst, const void* src){
    asm volatile("cp.async.cg.shared.global [%0], [%1], 16;" :: "r"(dst), "l"(src));
}
__device__ __forceinline__ void cp_commit(){
    asm volatile("cp.async.commit_group;" ::: "memory");
}
__device__ __forceinline__ void cp_wait0(){
    asm volatile("cp.async.wait_group 0;" ::: "memory");
}
__device__ __forceinline__ float sigmoidf_(float x){ return 1.0f / (1.0f + __expf(-x)); }
__device__ __forceinline__ uint16_t h16bits(float v){
    __half h = __float2half(v);
    return *reinterpret_cast<uint16_t*>(&h);
}

#define TSTRIDE 272u   // full-K (128) 16-bit tile row stride in bytes
#define HSTRIDE 144u   // half/quarter-K 16-bit tile row stride in bytes

// 32x(NTC*32) warp-tile single-term fp16 GEMM, KS ksteps.
template<int NTC, int KS, int SA, int SB>
__device__ __forceinline__ void gemm_f16(float (&acc)[2][NTC*4][4],
    uint32_t aBase, uint32_t bBase, int lane)
{
    const uint32_t aOff = (uint32_t)(lane & 15) * SA + (uint32_t)((lane >> 4) << 4);
    const uint32_t bOff = (uint32_t)(((lane >> 4) << 3) + (lane & 7)) * SB
                        + (uint32_t)(((lane >> 3) & 1) << 4);
    #pragma unroll
    for (int ks = 0; ks < KS; ks++) {
        const uint32_t ka = aOff + (uint32_t)ks * 32u;
        const uint32_t kb = bOff + (uint32_t)ks * 32u;
        uint32_t ah[2][4];
        ldsm_x4(ah[0], aBase + ka);
        ldsm_x4(ah[1], aBase + 16u * SA + ka);
        #pragma unroll
        for (int nc = 0; nc < NTC; nc++) {
            uint32_t bb[2][4];
            const uint32_t bn = (uint32_t)nc * 32u * SB + kb;
            ldsm_x4(bb[0], bBase + bn);
            ldsm_x4(bb[1], bBase + bn + 16u * SB);
            #pragma unroll
            for (int mt = 0; mt < 2; mt++)
                #pragma unroll
                for (int q = 0; q < 4; q++)
                    mma16816h(acc[mt][nc*4+q], ah[mt], &bb[q >> 1][(q & 1) << 1]);
        }
    }
}

// async copy one full fp16 weight tile (128 rows x 256 B, 272 stride), 256 threads
__device__ __forceinline__ void load_w_full(uint32_t dst, int mat){
    const unsigned char* src = g_wt + (size_t)mat * 34816;
    #pragma unroll
    for (int it = 0; it < 8; it++) {
        int lin = threadIdx.x + it * 256;      // 0..2047
        int r = lin >> 4, c = lin & 15;
        cp16(dst + (uint32_t)r * TSTRIDE + (uint32_t)c * 16u,
             src + (size_t)r * 272 + c * 16);
    }
    cp_commit();
}

// LN one row (128 cols) by a full warp; write fp16 into A tile (272B stride).
__device__ __forceinline__ void ln_row_f16(char* smp, uint32_t aOff,
    int row, int lane, const float* x,
    float g0, float g1, float g2, float g3,
    float c0, float c1, float c2, float c3)
{
    float v0 = x[lane], v1 = x[lane+32], v2 = x[lane+64], v3 = x[lane+96];
    float s = v0 + v1 + v2 + v3;
    #pragma unroll
    for (int o = 16; o > 0; o >>= 1) s += __shfl_xor_sync(0xffffffffu, s, o);
    float mean = s * (1.0f / 128.0f);
    float d0 = v0-mean, d1 = v1-mean, d2 = v2-mean, d3 = v3-mean;
    float q = d0*d0 + d1*d1 + d2*d2 + d3*d3;
    #pragma unroll
    for (int o = 16; o > 0; o >>= 1) q += __shfl_xor_sync(0xffffffffu, q, o);
    float inv = rsqrtf(q * (1.0f / 128.0f) + 1e-5f);
    uint16_t* aH = (uint16_t*)(smp + aOff);
    aH[row*136 + lane]      = h16bits(d0*inv*g0 + c0);
    aH[row*136 + lane + 32] = h16bits(d1*inv*g1 + c1);
    aH[row*136 + lane + 64] = h16bits(d2*inv*g2 + c2);
    aH[row*136 + lane + 96] = h16bits(d3*inv*g3 + c3);
}

// ============================================================
// Kernel W: pre-convert the 6 weight matrices to fp16 tile images
// (0=wga 1=wpa 2=wgb 3=wpb 4=wog 5=wop)
// ============================================================
__global__ void __launch_bounds__(512, 1) prep_w_kernel(
    const float* __restrict__ wga, const float* __restrict__ wpa,
    const float* __restrict__ wgb, const float* __restrict__ wpb,
    const float* __restrict__ wog, const float* __restrict__ wop)
{
    const float* Ws[6] = {wga, wpa, wgb, wpb, wog, wop};
    const float* W = Ws[blockIdx.x];
    unsigned char* dst = g_wt + (size_t)blockIdx.x * 34816;
    #pragma unroll
    for (int it = 0; it < 8; it++) {
        int lin = threadIdx.x + it * 512;
        int r = lin >> 5, c4 = (lin & 31) << 2;
        float4 v = *(const float4*)(W + r * 128 + c4);
        uint2 hh;
        hh.x = (uint32_t)h16bits(v.x) | ((uint32_t)h16bits(v.y) << 16);
        hh.y = (uint32_t)h16bits(v.z) | ((uint32_t)h16bits(v.w) << 16);
        *(uint2*)(dst + r * TSTRIDE + c4 * 2) = hh;
    }
}

// ============================================================
// Kernel P: LN(z) + 5 projections, fp16 single-term.  64 rows, 256 threads, 2 CTAs/SM.
// smem: A 0 (17408), WB0 17408 (34816), WB1 52224 (34816) = 87040.
// z stage (32768) overlays WB0; pair epilogue stage (18432) overlays WB0.
// ============================================================
#define PR_A   0u
#define PR_WB0 17408u
#define PR_WB1 52224u
#define PR_SMEM 87040

__global__ void __launch_bounds__(256, 2) proj_kernel(
    const float* __restrict__ z, const float* __restrict__ gin, const float* __restrict__ bin,
    const float* __restrict__ bga, const float* __restrict__ bpa,
    const float* __restrict__ bgb, const float* __restrict__ bpb,
    const float* __restrict__ bog)
{
    extern __shared__ char smp[];
    const uint32_t sb = smem_u32(smp);
    const int tid = threadIdx.x, wid = tid >> 5, lane = tid & 31;

    const size_t m0 = (size_t)blockIdx.x * 64;
    const int b  = (int)(m0 >> 16);
    const int ii = (int)((m0 >> 8) & 255);
    const int k0 = (int)(m0 & 255);

    // async prefetch: z tile -> WB0 stage [64][128] f32, wga -> WB1
    {
        const float* zsrc = z + m0 * 128;
        #pragma unroll
        for (int it = 0; it < 8; it++) {
            int lin = tid + it * 256;
            int r = lin >> 5, c = lin & 31;
            cp16(sb + PR_WB0 + (uint32_t)r * 512u + (uint32_t)c * 16u, zsrc + r * 128 + c * 4);
        }
        cp_commit();
    }
    load_w_full(sb + PR_WB1, 0);
    cp_wait0(); __syncthreads();

    {   // LN rows (from smem stage) -> fp16 A tile (8 rows per warp)
        const float* zs = (const float*)(smp + PR_WB0);
        const float g0 = gin[lane], g1 = gin[lane+32], g2 = gin[lane+64], g3 = gin[lane+96];
        const float c0 = bin[lane], c1 = bin[lane+32], c2 = bin[lane+64], c3 = bin[lane+96];
        #pragma unroll
        for (int r = 0; r < 8; r++) {
            int row = wid * 8 + r;
            ln_row_f16(smp, PR_A, row, lane, zs + row * 128,
                       g0, g1, g2, g3, c0, c1, c2, c3);
        }
    }
    __syncthreads();        // z stage consumed
    load_w_full(sb + PR_WB0, 1);     // wpa
    cp_wait0(); __syncthreads();

    const int m0w = (wid >> 2) * 32, n0w = (wid & 3) * 32;
    const uint32_t aW  = sb + PR_A + (uint32_t)m0w * TSTRIDE;
    const uint32_t w0n = sb + PR_WB0 + (uint32_t)n0w * TSTRIDE;
    const uint32_t w1n = sb + PR_WB1 + (uint32_t)n0w * TSTRIDE;

    // ---- two gated-pair phases (entry: WB1 = G mat, WB0 = P mat, no cp pending) ----
    for (int ph = 0; ph < 2; ph++) {
        const float* bg = ph ? bgb : bga;
        const float* bp = ph ? bpb : bpa;

        float accG[2][4][4] = {}, accP[2][4][4] = {};
        gemm_f16<1, 8, TSTRIDE, TSTRIDE>(accG, aW, w1n, lane);
        gemm_f16<1, 8, TSTRIDE, TSTRIDE>(accP, aW, w0n, lane);
        __syncthreads();                     // both W buffers dead

        load_w_full(sb + PR_WB1, ph ? 4 : 2);   // next G (wgb) or wog — overlaps epilogue

        // stage transposed into WB0: fp16 [d 128][m 72]
        uint16_t* stH = (uint16_t*)(smp + PR_WB0);
        #pragma unroll
        for (int mt = 0; mt < 2; mt++)
            #pragma unroll
            for (int q = 0; q < 4; q++) {
                int n = n0w + q * 8 + 2 * (lane & 3);
                float2 bg2 = *(const float2*)(bg + n);
                float2 bp2 = *(const float2*)(bp + n);
                #pragma unroll
                for (int rh = 0; rh < 2; rh++) {
                    int m = m0w + mt * 16 + (lane >> 2) + rh * 8;
                    float v0 = sigmoidf_(accG[mt][q][rh*2]   + bg2.x) * (accP[mt][q][rh*2]   + bp2.x);
                    float v1 = sigmoidf_(accG[mt][q][rh*2+1] + bg2.y) * (accP[mt][q][rh*2+1] + bp2.y);
                    stH[n * 72 + m]       = h16bits(v0);
                    stH[(n + 1) * 72 + m] = h16bits(v1);
                }
            }
        __syncthreads();

        __half* dst = ph ? g_bt : g_at;
        #pragma unroll
        for (int it = 0; it < 4; it++) {
            int lin = tid + it * 256;               // 0..1023
            int d = lin >> 3, m8 = (lin & 7) << 3;
            uint4 v = *(const uint4*)(smp + PR_WB0 + d * 144u + m8 * 2);
            *(uint4*)(dst + ((size_t)(b * 128 + d)) * 65536 + (size_t)ii * 256 + k0 + m8) = v;
        }
        __syncthreads();                            // stage consumed
        if (ph == 0) load_w_full(sb + PR_WB0, 3);   // wpb
        cp_wait0(); __syncthreads();
    }

    // ---- gate phase (WB1 = wog) ----
    float acc[2][4][4] = {};
    gemm_f16<1, 8, TSTRIDE, TSTRIDE>(acc, aW, w1n, lane);

    #pragma unroll
    for (int mt = 0; mt < 2; mt++)
        #pragma unroll
        for (int q = 0; q < 4; q++) {
            int n = n0w + q * 8 + 2 * (lane & 3);
            float2 bo2 = *(const float2*)(bog + n);
            #pragma unroll
            for (int rh = 0; rh < 2; rh++) {
                int m = m0w + mt * 16 + (lane >> 2) + rh * 8;
                __half2 o = __floats2half2_rn(sigmoidf_(acc[mt][q][rh*2]   + bo2.x),
                                              sigmoidf_(acc[mt][q][rh*2+1] + bo2.y));
                *(__half2*)(g_gate + (m0 + m) * 128 + n) = o;
            }
        }
}

// ============================================================
// Kernel T: triangle einsum, single-term fp16, WIDE tiles.
// C tile 64 x 256 (full j), 256 threads (8 warps, 2m x 4n, warp tile 32x64), 2 CTAs/SM.
// K = 256 in 4 chunks of 64, double-buffered (2 x 46080 = 92160 B).
// Chunk: A (64 rows, 144B stride) @0 (9216), B (256 rows) @9216 (36864).
// grid.x = 2048: bd = bx>>2, i0 = (bx&3)*64.
// ============================================================
#define TR_CHSZ 46080u
#define TR_SMEM 92160

__device__ __forceinline__ void tri_load_chunk(uint32_t bufBase, size_t base,
                                               int i0, int kc)
{
    #pragma unroll
    for (int it = 0; it < 10; it++) {
        int lin = threadIdx.x + it * 256;          // 0..2559
        if (lin < 512) {                           // A: 64 rows x 64 k fp16
            int r = lin >> 3, c = lin & 7;
            cp16(bufBase + (uint32_t)r * HSTRIDE + (uint32_t)c * 16u,
                 g_at + base + (size_t)(i0 + r) * 256 + kc * 64 + c * 8);
        } else {                                   // B: 256 rows x 64 k fp16
            int l2 = lin - 512;                    // 0..2047
            int r = l2 >> 3, c = l2 & 7;
            cp16(bufBase + 9216u + (uint32_t)r * HSTRIDE + (uint32_t)c * 16u,
                 g_bt + base + (size_t)r * 256 + kc * 64 + c * 8);
        }
    }
    cp_commit();
}

__global__ void __launch_bounds__(256, 2) tri_kernel()
{
    extern __shared__ char smp[];
    const uint32_t sb = smem_u32(smp);
    const int tid = threadIdx.x, wid = tid >> 5, lane = tid & 31;
    const int bx = blockIdx.x;
    const int bd = bx >> 2;
    const int i0 = (bx & 3) * 64;
    const size_t base = (size_t)bd * 65536;

    const int m0w = (wid >> 2) * 32, n0w = (wid & 3) * 64;
    float acc[2][8][4] = {};

    tri_load_chunk(sb, base, i0, 0);
    #pragma unroll
    for (int kc = 0; kc < 4; kc++) {
        cp_wait0(); __syncthreads();
        if (kc < 3) tri_load_chunk(sb + ((kc + 1) & 1) * TR_CHSZ, base, i0, kc + 1);
        const uint32_t bf = sb + (kc & 1) * TR_CHSZ;
        gemm_f16<2, 4, HSTRIDE, HSTRIDE>(acc,
            bf + (uint32_t)m0w * HSTRIDE,
            bf + 9216u + (uint32_t)n0w * HSTRIDE, lane);
    }

    #pragma unroll
    for (int mt = 0; mt < 2; mt++)
        #pragma unroll
        for (int nc = 0; nc < 2; nc++)
            #pragma unroll
            for (int q = 0; q < 4; q++) {
                int n = n0w + nc * 32 + q * 8 + 2 * (lane & 3);
                #pragma unroll
                for (int rh = 0; rh < 2; rh++) {
                    int m = m0w + mt * 16 + (lane >> 2) + rh * 8;
                    __half2 o = __floats2half2_rn(acc[mt][nc*4+q][rh*2], acc[mt][nc*4+q][rh*2+1]);
                    *(__half2*)(g_ot + base + (size_t)(i0 + m) * 256 + n) = o;
                }
            }
}

// ============================================================
// Kernel F: async gather + column-LN + wop + gate, fp16.  64 p-rows, 256 threads, 4 CTAs/SM.
// smem: A 0 (17408); S fp16 [128 d][72] @17408 (18432, dead after LN);
//       W overlays S @17408 (34816).  Total 52224.
// grid.x = 4096: b = bx>>10, p0 = (bx&1023)*64
// ============================================================
#define FN_A   0u
#define FN_S   17408u
#define FN_W   17408u
#define FN_SMEM 52224

__global__ void __launch_bounds__(256, 4) final_kernel(
    const float* __restrict__ gout, const float* __restrict__ bout,
    const float* __restrict__ bop, float* __restrict__ outp)
{
    extern __shared__ char smp[];
    const uint32_t sb = smem_u32(smp);
    const int tid = threadIdx.x, wid = tid >> 5, lane = tid & 31;
    const int b  = blockIdx.x >> 10;
    const int p0 = (blockIdx.x & 1023) * 64;

    // async raw gather: S[d][p] <- g_ot[b][d][p0 .. p0+63] fp16 (d-major, coalesced)
    {
        const __half* src = g_ot + (size_t)b * 128 * 65536 + p0;
        #pragma unroll
        for (int it = 0; it < 4; it++) {
            int lin = tid + it * 256;              // 0..1023 16B chunks
            int d = lin >> 3, c = lin & 7;
            cp16(sb + FN_S + (uint32_t)d * 144u + (uint32_t)c * 16u,
                 src + (size_t)d * 65536 + c * 8);
        }
        cp_commit();
    }
    cp_wait0(); __syncthreads();

    // column LN: warp w owns p = 8w..8w+7; 4 lanes per column (part = lane&3),
    // each lane covers d = part*32 + ((i + 2*part)&31).
    {
        const __half* S = (const __half*)(smp + FN_S);
        const int c  = lane >> 2, part = lane & 3;
        const int p  = wid * 8 + c;
        float s1 = 0.f;
        #pragma unroll
        for (int i = 0; i < 32; i++) {
            int d = part * 32 + ((i + 2 * part) & 31);
            s1 += __half2float(S[d * 72 + p]);
        }
        s1 += __shfl_xor_sync(0xffffffffu, s1, 1);
        s1 += __shfl_xor_sync(0xffffffffu, s1, 2);
        const float mean = s1 * (1.0f / 128.0f);
        float s2 = 0.f;
        #pragma unroll
        for (int i = 0; i < 32; i++) {
            int d = part * 32 + ((i + 2 * part) & 31);
            float v = __half2float(S[d * 72 + p]) - mean;
            s2 += v * v;
        }
        s2 += __shfl_xor_sync(0xffffffffu, s2, 1);
        s2 += __shfl_xor_sync(0xffffffffu, s2, 2);
        const float inv = rsqrtf(s2 * (1.0f / 128.0f) + 1e-5f);
        uint16_t* aH = (uint16_t*)(smp + FN_A);
        #pragma unroll
        for (int i = 0; i < 32; i++) {
            int d = part * 32 + ((i + 2 * part) & 31);
            float y = (__half2float(S[d * 72 + p]) - mean) * inv * gout[d] + bout[d];
            aH[p * 136 + d] = h16bits(y);
        }
    }
    __syncthreads();            // S consumed before W overlays it
    load_w_full(sb + FN_W, 5);
    cp_wait0(); __syncthreads();

    const int m0w = (wid >> 2) * 32, n0w = (wid & 3) * 32;
    float acc[2][4][4] = {};
    gemm_f16<1, 8, TSTRIDE, TSTRIDE>(acc, sb + FN_A + (uint32_t)m0w * TSTRIDE,
                                          sb + FN_W + (uint32_t)n0w * TSTRIDE, lane);

    #pragma unroll
    for (int mt = 0; mt < 2; mt++)
        #pragma unroll
        for (int q = 0; q < 4; q++) {
            int n = n0w + q * 8 + 2 * (lane & 3);
            float2 bo2 = *(const float2*)(bop + n);
            #pragma unroll
            for (int rh = 0; rh < 2; rh++) {
                int m = m0w + mt * 16 + (lane >> 2) + rh * 8;
                size_t gi = ((size_t)b * 65536 + p0 + m) * 128 + n;
                float2 g = __half22float2(*(const __half2*)(g_gate + gi));
                float2 o;
                o.x = g.x * (acc[mt][q][rh*2]   + bo2.x);
                o.y = g.y * (acc[mt][q][rh*2+1] + bo2.y);
                *(float2*)(outp + gi) = o;
            }
        }
}

// ============================================================
// launch
// ============================================================
extern "C" void kernel_launch(void* const* d_in, const int* in_sizes, int n_in,
                              void* d_out, int out_size)
{
    const float* z    = (const float*)d_in[0];
    const float* gin  = (const float*)d_in[1];
    const float* bin  = (const float*)d_in[2];
    const float* wpa  = (const float*)d_in[3];
    const float* bpa  = (const float*)d_in[4];
    const float* wga  = (const float*)d_in[5];
    const float* bga  = (const float*)d_in[6];
    const float* wpb  = (const float*)d_in[7];
    const float* bpb  = (const float*)d_in[8];
    const float* wgb  = (const float*)d_in[9];
    const float* bgb  = (const float*)d_in[10];
    const float* gout = (const float*)d_in[11];
    const float* bout = (const float*)d_in[12];
    const float* wop  = (const float*)d_in[13];
    const float* bop  = (const float*)d_in[14];
    const float* wog  = (const float*)d_in[15];
    const float* bog  = (const float*)d_in[16];
    float* outp = (float*)d_out;

    cudaFuncSetAttribute(proj_kernel,  cudaFuncAttributeMaxDynamicSharedMemorySize, PR_SMEM);
    cudaFuncSetAttribute(tri_kernel,   cudaFuncAttributeMaxDynamicSharedMemorySize, TR_SMEM);
    cudaFuncSetAttribute(final_kernel, cudaFuncAttributeMaxDynamicSharedMemorySize, FN_SMEM);

    prep_w_kernel<<<6, 512>>>(wga, wpa, wgb, wpb, wog, wop);
    proj_kernel<<<4096, 256, PR_SMEM>>>(z, gin, bin, bga, bpa, bgb, bpb, bog);
    tri_kernel<<<2048, 256, TR_SMEM>>>();
    final_kernel<<<4096, 256, FN_SMEM>>>(gout, bout, bop, outp);
}